// round 7
// baseline (speedup 1.0000x reference)
#include <cuda_runtime.h>
#include <cuda_bf16.h>
#include <cstdint>

// ---------------------------------------------------------------------------
// Classifier: out[e] = MLP(concat(x_drug[i_e], x_disease[j_e]))
// Layer-1 factored per-node (fp32):
//   h_drug    = x_drug    @ W1[0:100]   + b1     (n_drug x 128)
//   h_disease = x_disease @ W1[100:200]          (n_dis  x 128)
// Per edge: h = leaky(h_drug[i]+h_disease[j]) assembled DIRECTLY into
// mma.m16n8k8 tf32 A-fragments (no smem staging); layer-2 (128->32) and
// layer-3 (32->16) both on tensor cores with register-resident weights;
// layer-4 dot + shfl reduce. Warp-autonomous, no per-tile block syncs.
// ---------------------------------------------------------------------------

typedef unsigned long long ull;

#define MAX_NODES 16384
__device__ float g_hd[MAX_NODES * 128];
__device__ float g_he[MAX_NODES * 128];
__device__ int   g_idx64;   // 1 if edge index buffer is int64, 0 if int32

__device__ __forceinline__ float lrelu(float v) {
    return v >= 0.0f ? v : 0.01f * v;
}
__device__ __forceinline__ ull pk2(float a, float b) {
    ull r;
    asm("mov.b64 %0, {%1, %2};" : "=l"(r) : "f"(a), "f"(b));
    return r;
}
__device__ __forceinline__ void up2(ull v, float& a, float& b) {
    asm("mov.b64 {%0, %1}, %2;" : "=f"(a), "=f"(b) : "l"(v));
}
__device__ __forceinline__ ull fma2(ull a, ull b, ull c) {
    ull d;
    asm("fma.rn.f32x2 %0, %1, %2, %3;" : "=l"(d) : "l"(a), "l"(b), "l"(c));
    return d;
}
__device__ __forceinline__ uint32_t f2tf32(float f) {
    uint32_t r;
    asm("cvt.rna.tf32.f32 %0, %1;" : "=r"(r) : "f"(f));
    return r;
}
__device__ __forceinline__ long long load_idx(const void* ell, long long pos,
                                              int is64) {
    if (is64) return ((const long long*)ell)[pos];
    return (long long)((const int*)ell)[pos];
}

// m16n8k8 tf32 MMA (row.col), D/C fp32 in-place accumulate
__device__ __forceinline__ void mma8(float d[4], uint32_t a0, uint32_t a1,
                                     uint32_t a2, uint32_t a3,
                                     uint32_t b0, uint32_t b1) {
    asm volatile(
        "mma.sync.aligned.m16n8k8.row.col.f32.tf32.tf32.f32 "
        "{%0,%1,%2,%3}, {%4,%5,%6,%7}, {%8,%9}, {%0,%1,%2,%3};"
        : "+f"(d[0]), "+f"(d[1]), "+f"(d[2]), "+f"(d[3])
        : "r"(a0), "r"(a1), "r"(a2), "r"(a3), "r"(b0), "r"(b1));
}

// ---------------------------------------------------------------------------
// Kernel 1: tiled layer-1 precompute (16 nodes/block, W1 slice in smem).
// Block 0 thread 0 also detects the edge-index dtype (JAX w/o x64 -> int32).
// ---------------------------------------------------------------------------
#define NB 16
__global__ void __launch_bounds__(256, 3)
node_precompute(const float* __restrict__ xd,
                const float* __restrict__ xs,
                const float* __restrict__ W1,
                const float* __restrict__ b1,
                const long long* __restrict__ ell,
                int n_drug, int n_dis, int nb_drug) {
    extern __shared__ float nsm[];
    float* w1s  = nsm;              // 100*128
    float* xsh2 = nsm + 12800;      // 100*16, [k][node]

    const int tid = threadIdx.x;
    const int bid = blockIdx.x;

    if (bid == 0 && tid == 0) {
        int ok64 = 1;
#pragma unroll
        for (int t = 0; t < 8; t++) {
            long long v = ell[t];
            if (v < 0 || v >= 1000000) ok64 = 0;
        }
        g_idx64 = ok64;
    }

    const bool is_drug = bid < nb_drug;
    const int  n       = is_drug ? n_drug : n_dis;
    const int  nbase   = (is_drug ? bid : bid - nb_drug) * NB;
    const float* x   = is_drug ? xd : xs;
    const float* w   = W1 + (is_drug ? 0 : 100 * 128);
    float*       out = is_drug ? g_hd : g_he;

    for (int i = tid; i < 100 * 128; i += 256) w1s[i] = w[i];
    for (int i = tid; i < NB * 100; i += 256) {
        int node = i & (NB - 1);
        int k    = i >> 4;
        int gn   = nbase + node;
        xsh2[k * NB + node] = (gn < n) ? x[(long)gn * 100 + k] : 0.0f;
    }
    __syncthreads();

    const int m = tid & 127;
    const int g = tid >> 7;

    float bm = is_drug ? b1[m] : 0.0f;
    ull acc[4];
#pragma unroll
    for (int p = 0; p < 4; p++) acc[p] = pk2(bm, bm);

#pragma unroll 4
    for (int k = 0; k < 100; k++) {
        float wv = w1s[k * 128 + m];
        ull w2 = pk2(wv, wv);
        float4 xa = *(const float4*)&xsh2[k * NB + 8 * g];
        float4 xb = *(const float4*)&xsh2[k * NB + 8 * g + 4];
        acc[0] = fma2(pk2(xa.x, xa.y), w2, acc[0]);
        acc[1] = fma2(pk2(xa.z, xa.w), w2, acc[1]);
        acc[2] = fma2(pk2(xb.x, xb.y), w2, acc[2]);
        acc[3] = fma2(pk2(xb.z, xb.w), w2, acc[3]);
    }

#pragma unroll
    for (int p = 0; p < 4; p++) {
        float a, b;
        up2(acc[p], a, b);
        int n0 = nbase + 8 * g + 2 * p;
        if (n0 < n)     out[(long)n0 * 128 + m]       = a;
        if (n0 + 1 < n) out[(long)(n0 + 1) * 128 + m] = b;
    }
}

// ---------------------------------------------------------------------------
// Kernel 2: persistent per-edge MLP, warp-autonomous, register-resident.
// Block = 256 threads (8 warps), tile = 128 edges, warp owns 16 edges.
// smem holds only W2 B-fragments (16 KB, staged once).
// ---------------------------------------------------------------------------
#define EPB   128
#define NTHR  256

__global__ void __launch_bounds__(NTHR, 3)
edge_mlp_kernel(const void* __restrict__ ell,
                const float* __restrict__ W2, const float* __restrict__ b2,
                const float* __restrict__ W3, const float* __restrict__ b3,
                const float* __restrict__ W4, const float* __restrict__ b4,
                float* __restrict__ out, int E, int n_tiles) {
    __shared__ uint32_t bfr[4096];   // W2 B-frags: [16 ks][4 nb][32 lane][2]

    const int tid  = threadIdx.x;
    const int warp = tid >> 5;
    const int lane = tid & 31;
    const int is64 = g_idx64;

    // ---- stage W2 B-fragments once ----
    // value r at lane ln for (ks,nb): tf32(W2[(ks*8 + ln%4 + 4r)*32 + nb*8 + ln/4])
    for (int idx = tid; idx < 4096; idx += NTHR) {
        int r  = idx & 1;
        int ln = (idx >> 1) & 31;
        int nb = (idx >> 6) & 3;
        int ks = idx >> 8;
        int k  = ks * 8 + (ln & 3) + 4 * r;
        int n  = nb * 8 + (ln >> 2);
        bfr[idx] = f2tf32(W2[k * 32 + n]);
    }
    __syncthreads();

    const int g    = lane >> 2;        // 0..7
    const int c    = lane & 3;         // 0..3
    const int src  = (lane & 28) | (c >> 1);   // 4g + (c>>1)
    const int src2 = src + 2;
    const bool codd = (c & 1);

    // ---- per-lane register-resident constants ----
    float b2r[4][2], b3r[2][2], w4r[2][2];
#pragma unroll
    for (int nb = 0; nb < 4; nb++) {
        b2r[nb][0] = __ldg(&b2[8 * nb + 2 * c + 0]);
        b2r[nb][1] = __ldg(&b2[8 * nb + 2 * c + 1]);
    }
#pragma unroll
    for (int o = 0; o < 2; o++) {
        b3r[o][0] = __ldg(&b3[8 * o + 2 * c + 0]);
        b3r[o][1] = __ldg(&b3[8 * o + 2 * c + 1]);
        w4r[o][0] = __ldg(&W4[8 * o + 2 * c + 0]);
        w4r[o][1] = __ldg(&W4[8 * o + 2 * c + 1]);
    }
    // W3 B-frags in registers: w3f[kb][o] = {tf32(W3[(8kb+c)*16 + 8o+g]),
    //                                        tf32(W3[(8kb+c+4)*16 + 8o+g])}
    uint32_t w3f[4][2][2];
#pragma unroll
    for (int kb = 0; kb < 4; kb++)
#pragma unroll
        for (int o = 0; o < 2; o++) {
            w3f[kb][o][0] = f2tf32(__ldg(&W3[(8 * kb + c) * 16 + 8 * o + g]));
            w3f[kb][o][1] = f2tf32(__ldg(&W3[(8 * kb + c + 4) * 16 + 8 * o + g]));
        }
    const float b4v = __ldg(&b4[0]);
    const uint2* bfl = (const uint2*)bfr + lane;

    for (int tile = blockIdx.x; tile < n_tiles; tile += gridDim.x) {
        const int ebase = tile * EPB + warp * 16;

        // ---- indices -> 4 row base pointers per lane ----
        {
            int e  = ebase + (lane & 15);
            int ec = e < E ? e : (E - 1);
            long long pos = (lane < 16) ? (long long)ec : (long long)E + ec;
            long long v = load_idx(ell, pos, is64);

            long long iG  = __shfl_sync(0xffffffffu, v, g);
            long long iG8 = __shfl_sync(0xffffffffu, v, g + 8);
            long long jG  = __shfl_sync(0xffffffffu, v, 16 + g);
            long long jG8 = __shfl_sync(0xffffffffu, v, 24 + g);

            const float* pd0 = g_hd + iG  * 128 + c;
            const float* pd1 = g_hd + iG8 * 128 + c;
            const float* pe0 = g_he + jG  * 128 + c;
            const float* pe1 = g_he + jG8 * 128 + c;

            // ---- layer 2: gather straight into A-frags + mma ----
            float acc[4][4];
#pragma unroll
            for (int nb = 0; nb < 4; nb++)
#pragma unroll
                for (int q = 0; q < 4; q++) acc[nb][q] = 0.0f;

#pragma unroll
            for (int ks = 0; ks < 16; ks++) {
                float x0 = pd0[8 * ks]     + pe0[8 * ks];
                float x1 = pd1[8 * ks]     + pe1[8 * ks];
                float x2 = pd0[8 * ks + 4] + pe0[8 * ks + 4];
                float x3 = pd1[8 * ks + 4] + pe1[8 * ks + 4];
                uint32_t a0 = f2tf32(lrelu(x0));
                uint32_t a1 = f2tf32(lrelu(x1));
                uint32_t a2 = f2tf32(lrelu(x2));
                uint32_t a3 = f2tf32(lrelu(x3));
#pragma unroll
                for (int nb = 0; nb < 4; nb++) {
                    uint2 bb = bfl[(ks * 4 + nb) * 32];
                    mma8(acc[nb], a0, a1, a2, a3, bb.x, bb.y);
                }
            }

            // ---- layer 3: bias+leaky, permute acc -> A-frags, mma ----
            float acc3[2][4];
#pragma unroll
            for (int o = 0; o < 2; o++)
#pragma unroll
                for (int q = 0; q < 4; q++) acc3[o][q] = 0.0f;

#pragma unroll
            for (int kb = 0; kb < 4; kb++) {
                uint32_t xa0 = f2tf32(lrelu(acc[kb][0] + b2r[kb][0]));
                uint32_t xa1 = f2tf32(lrelu(acc[kb][1] + b2r[kb][1]));
                uint32_t xb0 = f2tf32(lrelu(acc[kb][2] + b2r[kb][0]));
                uint32_t xb1 = f2tf32(lrelu(acc[kb][3] + b2r[kb][1]));

                uint32_t u0 = __shfl_sync(0xffffffffu, xa0, src);
                uint32_t u1 = __shfl_sync(0xffffffffu, xa1, src);
                uint32_t a0 = codd ? u1 : u0;
                uint32_t v0 = __shfl_sync(0xffffffffu, xb0, src);
                uint32_t v1 = __shfl_sync(0xffffffffu, xb1, src);
                uint32_t a1 = codd ? v1 : v0;
                uint32_t s0 = __shfl_sync(0xffffffffu, xa0, src2);
                uint32_t s1 = __shfl_sync(0xffffffffu, xa1, src2);
                uint32_t a2 = codd ? s1 : s0;
                uint32_t t0 = __shfl_sync(0xffffffffu, xb0, src2);
                uint32_t t1 = __shfl_sync(0xffffffffu, xb1, src2);
                uint32_t a3 = codd ? t1 : t0;

                mma8(acc3[0], a0, a1, a2, a3, w3f[kb][0][0], w3f[kb][0][1]);
                mma8(acc3[1], a0, a1, a2, a3, w3f[kb][1][0], w3f[kb][1][1]);
            }

            // ---- layer 4: bias+leaky, dot with w4, shfl-reduce over c ----
            float y0 = 0.0f, y1 = 0.0f;
#pragma unroll
            for (int o = 0; o < 2; o++) {
                y0 = fmaf(lrelu(acc3[o][0] + b3r[o][0]), w4r[o][0], y0);
                y0 = fmaf(lrelu(acc3[o][1] + b3r[o][1]), w4r[o][1], y0);
                y1 = fmaf(lrelu(acc3[o][2] + b3r[o][0]), w4r[o][0], y1);
                y1 = fmaf(lrelu(acc3[o][3] + b3r[o][1]), w4r[o][1], y1);
            }
            y0 += __shfl_xor_sync(0xffffffffu, y0, 1);
            y0 += __shfl_xor_sync(0xffffffffu, y0, 2);
            y1 += __shfl_xor_sync(0xffffffffu, y1, 1);
            y1 += __shfl_xor_sync(0xffffffffu, y1, 2);

            if (c == 0) {
                int e0 = ebase + g;
                if (e0 < E)     out[e0]     = y0 + b4v;
                if (e0 + 8 < E) out[e0 + 8] = y1 + b4v;
            }
        }
    }
}

// ---------------------------------------------------------------------------
extern "C" void kernel_launch(void* const* d_in, const int* in_sizes, int n_in,
                              void* d_out, int out_size) {
    const float* xd  = (const float*)d_in[0];
    const float* xs  = (const float*)d_in[1];
    const void*  ell = d_in[2];
    const float* W1  = (const float*)d_in[3];
    const float* b1  = (const float*)d_in[4];
    const float* W2  = (const float*)d_in[5];
    const float* b2  = (const float*)d_in[6];
    const float* W3  = (const float*)d_in[7];
    const float* b3  = (const float*)d_in[8];
    const float* W4  = (const float*)d_in[9];
    const float* b4  = (const float*)d_in[10];
    float* out = (float*)d_out;

    int n_drug = in_sizes[0] / 100;
    int n_dis  = in_sizes[1] / 100;
    int E      = in_sizes[2] / 2;

    int nb_drug = (n_drug + NB - 1) / NB;
    int nb_dis  = (n_dis  + NB - 1) / NB;
    int node_smem = (12800 + 100 * NB) * 4;
    cudaFuncSetAttribute(node_precompute,
                         cudaFuncAttributeMaxDynamicSharedMemorySize, node_smem);
    node_precompute<<<nb_drug + nb_dis, 256, node_smem>>>(
        xd, xs, W1, b1, (const long long*)ell, n_drug, n_dis, nb_drug);

    int n_tiles = (E + EPB - 1) / EPB;
    int grid = 3 * 148;
    if (grid > n_tiles) grid = n_tiles;
    edge_mlp_kernel<<<grid, NTHR>>>(ell, W2, b2, W3, b3, W4, b4,
                                    out, E, n_tiles);
}

// round 9
// speedup vs baseline: 2.5914x; 2.5914x over previous
#include <cuda_runtime.h>
#include <cuda_bf16.h>
#include <cuda_fp16.h>
#include <cstdint>

// ---------------------------------------------------------------------------
// Classifier: out[e] = MLP(concat(x_drug[i_e], x_disease[j_e]))
// Layer-1 factored per-node (fp32):
//   h_drug    = x_drug    @ W1[0:100]   + b1     (n_drug x 128)
//   h_disease = x_disease @ W1[100:200]          (n_dis  x 128)
// Per edge: h = leaky(h_drug[i]+h_disease[j]) -> fp16 smem; layer-2 (128->32)
// and layer-3 (32->16) on mma.m16n8k16.f16 (fp32 accum) whose fragment
// layouts compose (layer-2 D == layer-3 A: zero shuffles); layer-4 dot +
// shfl reduce. Warp-autonomous: no per-tile block syncs.
// ---------------------------------------------------------------------------

typedef unsigned long long ull;

#define MAX_NODES 16384
__device__ float g_hd[MAX_NODES * 128];
__device__ float g_he[MAX_NODES * 128];
__device__ int   g_idx64;   // 1 if edge index buffer is int64, 0 if int32

__device__ __forceinline__ float lrelu(float v) {
    return v >= 0.0f ? v : 0.01f * v;
}
__device__ __forceinline__ ull pk2(float a, float b) {
    ull r;
    asm("mov.b64 %0, {%1, %2};" : "=l"(r) : "f"(a), "f"(b));
    return r;
}
__device__ __forceinline__ void up2(ull v, float& a, float& b) {
    asm("mov.b64 {%0, %1}, %2;" : "=f"(a), "=f"(b) : "l"(v));
}
__device__ __forceinline__ ull fma2(ull a, ull b, ull c) {
    ull d;
    asm("fma.rn.f32x2 %0, %1, %2, %3;" : "=l"(d) : "l"(a), "l"(b), "l"(c));
    return d;
}
__device__ __forceinline__ uint32_t h2(float a, float b) {
    __half2 h = __floats2half2_rn(a, b);   // x(lo)=a, y(hi)=b
    return *(uint32_t*)&h;
}
__device__ __forceinline__ long long load_idx(const void* ell, long long pos,
                                              int is64) {
    if (is64) return ((const long long*)ell)[pos];
    return (long long)((const int*)ell)[pos];
}

// m16n8k16 f16 MMA (row.col), fp32 accumulate in place
__device__ __forceinline__ void hmma16(float d[4], uint32_t a0, uint32_t a1,
                                       uint32_t a2, uint32_t a3,
                                       uint32_t b0, uint32_t b1) {
    asm volatile(
        "mma.sync.aligned.m16n8k16.row.col.f32.f16.f16.f32 "
        "{%0,%1,%2,%3}, {%4,%5,%6,%7}, {%8,%9}, {%0,%1,%2,%3};"
        : "+f"(d[0]), "+f"(d[1]), "+f"(d[2]), "+f"(d[3])
        : "r"(a0), "r"(a1), "r"(a2), "r"(a3), "r"(b0), "r"(b1));
}

// ---------------------------------------------------------------------------
// Kernel 1: tiled layer-1 precompute (16 nodes/block, W1 slice in smem).
// Block 0 thread 0 also detects the edge-index dtype (JAX w/o x64 -> int32).
// ---------------------------------------------------------------------------
#define NB 16
__global__ void __launch_bounds__(256, 3)
node_precompute(const float* __restrict__ xd,
                const float* __restrict__ xs,
                const float* __restrict__ W1,
                const float* __restrict__ b1,
                const long long* __restrict__ ell,
                int n_drug, int n_dis, int nb_drug) {
    extern __shared__ float nsm[];
    float* w1s  = nsm;              // 100*128
    float* xsh2 = nsm + 12800;      // 100*16, [k][node]

    const int tid = threadIdx.x;
    const int bid = blockIdx.x;

    if (bid == 0 && tid == 0) {
        int ok64 = 1;
#pragma unroll
        for (int t = 0; t < 8; t++) {
            long long v = ell[t];
            if (v < 0 || v >= 1000000) ok64 = 0;
        }
        g_idx64 = ok64;
    }

    const bool is_drug = bid < nb_drug;
    const int  n       = is_drug ? n_drug : n_dis;
    const int  nbase   = (is_drug ? bid : bid - nb_drug) * NB;
    const float* x   = is_drug ? xd : xs;
    const float* w   = W1 + (is_drug ? 0 : 100 * 128);
    float*       out = is_drug ? g_hd : g_he;

    for (int i = tid; i < 100 * 128; i += 256) w1s[i] = w[i];
    for (int i = tid; i < NB * 100; i += 256) {
        int node = i & (NB - 1);
        int k    = i >> 4;
        int gn   = nbase + node;
        xsh2[k * NB + node] = (gn < n) ? x[(long)gn * 100 + k] : 0.0f;
    }
    __syncthreads();

    const int m = tid & 127;
    const int g = tid >> 7;

    float bm = is_drug ? b1[m] : 0.0f;
    ull acc[4];
#pragma unroll
    for (int p = 0; p < 4; p++) acc[p] = pk2(bm, bm);

#pragma unroll 4
    for (int k = 0; k < 100; k++) {
        float wv = w1s[k * 128 + m];
        ull w2 = pk2(wv, wv);
        float4 xa = *(const float4*)&xsh2[k * NB + 8 * g];
        float4 xb = *(const float4*)&xsh2[k * NB + 8 * g + 4];
        acc[0] = fma2(pk2(xa.x, xa.y), w2, acc[0]);
        acc[1] = fma2(pk2(xa.z, xa.w), w2, acc[1]);
        acc[2] = fma2(pk2(xb.x, xb.y), w2, acc[2]);
        acc[3] = fma2(pk2(xb.z, xb.w), w2, acc[3]);
    }

#pragma unroll
    for (int p = 0; p < 4; p++) {
        float a, b;
        up2(acc[p], a, b);
        int n0 = nbase + 8 * g + 2 * p;
        if (n0 < n)     out[(long)n0 * 128 + m]       = a;
        if (n0 + 1 < n) out[(long)(n0 + 1) * 128 + m] = b;
    }
}

// ---------------------------------------------------------------------------
// Kernel 2: persistent per-edge MLP, warp-autonomous, fp16 tensor path.
// Block = 256 threads (8 warps), tile = 128 edges, warp owns 16 edges.
// smem: per-warp hs (16 rows x 128 fp16, row stride 272B -> conflict-free)
//       + W2 B-fragments (fp16, 8 KB).
// ---------------------------------------------------------------------------
#define EPB   128
#define NTHR  256
#define HS_RS 272                       // bytes per hs row (256 + 16 pad)

__global__ void __launch_bounds__(NTHR, 3)
edge_mlp_kernel(const void* __restrict__ ell,
                const float* __restrict__ W2, const float* __restrict__ b2,
                const float* __restrict__ W3, const float* __restrict__ b3,
                const float* __restrict__ W4, const float* __restrict__ b4,
                float* __restrict__ out, int E, int n_tiles) {
    __shared__ char  hsraw[8 * 16 * HS_RS];   // 34816 B
    __shared__ uint2 wfr[8 * 4 * 32];         // W2 frags: [ks8][nb4][lane] 8 KB

    const int tid  = threadIdx.x;
    const int warp = tid >> 5;
    const int lane = tid & 31;
    const int is64 = g_idx64;

    // ---- stage W2 fp16 B-fragments once ----
    // (ks,nb,lane): n = 8nb + lane/4, kb = 16ks + 2*(lane%4)
    //   .x = half2(W2[kb][n],   W2[kb+1][n])
    //   .y = half2(W2[kb+8][n], W2[kb+9][n])
    for (int idx = tid; idx < 1024; idx += NTHR) {
        int ln = idx & 31;
        int nb = (idx >> 5) & 3;
        int ks = idx >> 7;
        int n  = 8 * nb + (ln >> 2);
        int kb = 16 * ks + 2 * (ln & 3);
        uint2 b;
        b.x = h2(W2[kb * 32 + n],       W2[(kb + 1) * 32 + n]);
        b.y = h2(W2[(kb + 8) * 32 + n], W2[(kb + 9) * 32 + n]);
        wfr[idx] = b;
    }
    __syncthreads();

    const int g = lane >> 2;        // 0..7
    const int c = lane & 3;         // 0..3

    // ---- register-resident constants ----
    float b2r[4][2];
#pragma unroll
    for (int nb = 0; nb < 4; nb++) {
        b2r[nb][0] = __ldg(&b2[8 * nb + 2 * c + 0]);
        b2r[nb][1] = __ldg(&b2[8 * nb + 2 * c + 1]);
    }
    // W3 fp16 B-frags (layer-3): [ks3][nb3] -> {b0,b1}
    uint32_t w3f[2][2][2];
#pragma unroll
    for (int ks3 = 0; ks3 < 2; ks3++)
#pragma unroll
        for (int nb3 = 0; nb3 < 2; nb3++) {
            int n  = 8 * nb3 + g;
            int kb = 16 * ks3 + 2 * c;
            w3f[ks3][nb3][0] = h2(__ldg(&W3[kb * 16 + n]),
                                  __ldg(&W3[(kb + 1) * 16 + n]));
            w3f[ks3][nb3][1] = h2(__ldg(&W3[(kb + 8) * 16 + n]),
                                  __ldg(&W3[(kb + 9) * 16 + n]));
        }
    float b3r[2][2], w4r[2][2];
#pragma unroll
    for (int o = 0; o < 2; o++) {
        b3r[o][0] = __ldg(&b3[8 * o + 2 * c + 0]);
        b3r[o][1] = __ldg(&b3[8 * o + 2 * c + 1]);
        w4r[o][0] = __ldg(&W4[8 * o + 2 * c + 0]);
        w4r[o][1] = __ldg(&W4[8 * o + 2 * c + 1]);
    }
    const float b4v = __ldg(&b4[0]);

    char* hw = hsraw + warp * 16 * HS_RS;

    for (int tile = blockIdx.x; tile < n_tiles; tile += gridDim.x) {
        const int ebase = tile * EPB + warp * 16;

        // ---- phase 1: coalesced gather + combine + leaky -> fp16 smem ----
        {
            int e  = ebase + (lane & 15);
            int ec = e < E ? e : (E - 1);
            long long pos = (lane < 16) ? (long long)ec : (long long)E + ec;
            long long v = load_idx(ell, pos, is64);

#pragma unroll
            for (int t = 0; t < 16; t++) {
                long long i = __shfl_sync(0xffffffffu, v, t);
                long long j = __shfl_sync(0xffffffffu, v, 16 + t);
                const float4 a = *(const float4*)&g_hd[i * 128 + lane * 4];
                const float4 b = *(const float4*)&g_he[j * 128 + lane * 4];
                uint2 s;
                s.x = h2(lrelu(a.x + b.x), lrelu(a.y + b.y));
                s.y = h2(lrelu(a.z + b.z), lrelu(a.w + b.w));
                *(uint2*)(hw + t * HS_RS + lane * 8) = s;
            }
        }
        __syncwarp();

        // ---- phase 2: layer-2 mma (8 k16-steps x 4 n-blocks) ----
        float acc[4][4];
#pragma unroll
        for (int nb = 0; nb < 4; nb++)
#pragma unroll
            for (int q = 0; q < 4; q++) acc[nb][q] = 0.0f;

        {
            const char* r0 = hw + g * HS_RS + 4 * c;          // row g
            const char* r1 = r0 + 8 * HS_RS;                  // row g+8
#pragma unroll
            for (int ks = 0; ks < 8; ks++) {
                uint32_t a0 = *(const uint32_t*)(r0 + 32 * ks);
                uint32_t a1 = *(const uint32_t*)(r1 + 32 * ks);
                uint32_t a2 = *(const uint32_t*)(r0 + 32 * ks + 16);
                uint32_t a3 = *(const uint32_t*)(r1 + 32 * ks + 16);
#pragma unroll
                for (int nb = 0; nb < 4; nb++) {
                    uint2 bb = wfr[(ks * 4 + nb) * 32 + lane];
                    hmma16(acc[nb], a0, a1, a2, a3, bb.x, bb.y);
                }
            }
        }
        __syncwarp();    // hs consumed; safe to rewrite next tile

        // ---- phase 3: layer-3 mma — layer-2 D frag IS layer-3 A frag ----
        float acc3[2][4];
#pragma unroll
        for (int o = 0; o < 2; o++)
#pragma unroll
            for (int q = 0; q < 4; q++) acc3[o][q] = 0.0f;

#pragma unroll
        for (int ks3 = 0; ks3 < 2; ks3++) {
            const int nbA = 2 * ks3;       // k-cols 16ks3..16ks3+7
            const int nbB = 2 * ks3 + 1;   // k-cols 16ks3+8..16ks3+15
            uint32_t a0 = h2(lrelu(acc[nbA][0] + b2r[nbA][0]),
                             lrelu(acc[nbA][1] + b2r[nbA][1]));
            uint32_t a1 = h2(lrelu(acc[nbA][2] + b2r[nbA][0]),
                             lrelu(acc[nbA][3] + b2r[nbA][1]));
            uint32_t a2 = h2(lrelu(acc[nbB][0] + b2r[nbB][0]),
                             lrelu(acc[nbB][1] + b2r[nbB][1]));
            uint32_t a3 = h2(lrelu(acc[nbB][2] + b2r[nbB][0]),
                             lrelu(acc[nbB][3] + b2r[nbB][1]));
#pragma unroll
            for (int nb3 = 0; nb3 < 2; nb3++)
                hmma16(acc3[nb3], a0, a1, a2, a3,
                       w3f[ks3][nb3][0], w3f[ks3][nb3][1]);
        }

        // ---- phase 4: bias+leaky, dot W4, shfl-reduce over c, store ----
        {
            float y0 = 0.0f, y1 = 0.0f;
#pragma unroll
            for (int o = 0; o < 2; o++) {
                y0 = fmaf(lrelu(acc3[o][0] + b3r[o][0]), w4r[o][0], y0);
                y0 = fmaf(lrelu(acc3[o][1] + b3r[o][1]), w4r[o][1], y0);
                y1 = fmaf(lrelu(acc3[o][2] + b3r[o][0]), w4r[o][0], y1);
                y1 = fmaf(lrelu(acc3[o][3] + b3r[o][1]), w4r[o][1], y1);
            }
            y0 += __shfl_xor_sync(0xffffffffu, y0, 1);
            y0 += __shfl_xor_sync(0xffffffffu, y0, 2);
            y1 += __shfl_xor_sync(0xffffffffu, y1, 1);
            y1 += __shfl_xor_sync(0xffffffffu, y1, 2);

            if (c == 0) {
                int e0 = ebase + g;
                if (e0 < E)     out[e0]     = y0 + b4v;
                if (e0 + 8 < E) out[e0 + 8] = y1 + b4v;
            }
        }
    }
}

// ---------------------------------------------------------------------------
extern "C" void kernel_launch(void* const* d_in, const int* in_sizes, int n_in,
                              void* d_out, int out_size) {
    const float* xd  = (const float*)d_in[0];
    const float* xs  = (const float*)d_in[1];
    const void*  ell = d_in[2];
    const float* W1  = (const float*)d_in[3];
    const float* b1  = (const float*)d_in[4];
    const float* W2  = (const float*)d_in[5];
    const float* b2  = (const float*)d_in[6];
    const float* W3  = (const float*)d_in[7];
    const float* b3  = (const float*)d_in[8];
    const float* W4  = (const float*)d_in[9];
    const float* b4  = (const float*)d_in[10];
    float* out = (float*)d_out;

    int n_drug = in_sizes[0] / 100;
    int n_dis  = in_sizes[1] / 100;
    int E      = in_sizes[2] / 2;

    int nb_drug = (n_drug + NB - 1) / NB;
    int nb_dis  = (n_dis  + NB - 1) / NB;
    int node_smem = (12800 + 100 * NB) * 4;
    cudaFuncSetAttribute(node_precompute,
                         cudaFuncAttributeMaxDynamicSharedMemorySize, node_smem);
    node_precompute<<<nb_drug + nb_dis, 256, node_smem>>>(
        xd, xs, W1, b1, (const long long*)ell, n_drug, n_dis, nb_drug);

    int n_tiles = (E + EPB - 1) / EPB;
    int grid = 3 * 148;
    if (grid > n_tiles) grid = n_tiles;
    edge_mlp_kernel<<<grid, NTHR>>>(ell, W2, b2, W3, b3, W4, b4,
                                    out, E, n_tiles);
}

// round 10
// speedup vs baseline: 3.0669x; 1.1835x over previous
#include <cuda_runtime.h>
#include <cuda_bf16.h>
#include <cuda_fp16.h>
#include <cstdint>

// ---------------------------------------------------------------------------
// Classifier: out[e] = MLP(concat(x_drug[i_e], x_disease[j_e]))
// Layer-1 factored per-node (fp32 compute, fp16 storage):
//   h_drug    = x_drug    @ W1[0:100]   + b1     (n_drug x 128)
//   h_disease = x_disease @ W1[100:200]          (n_dis  x 128)
// Per edge: h = leaky(h_drug[i]+h_disease[j]) (fp32 add) -> fp16 smem;
// layer-2 (128->32) and layer-3 (32->16) on mma.m16n8k16.f16 (fp32 accum)
// with composing fragment layouts (layer-2 D == layer-3 A, zero shuffles);
// layer-4 dot + shfl reduce. Warp-autonomous: no per-tile block syncs.
// ---------------------------------------------------------------------------

typedef unsigned long long ull;

#define MAX_NODES 16384
__device__ __half g_hd[MAX_NODES * 128];
__device__ __half g_he[MAX_NODES * 128];
__device__ int    g_idx64;   // 1 if edge index buffer is int64, 0 if int32

__device__ __forceinline__ float lrelu(float v) {
    return v >= 0.0f ? v : 0.01f * v;
}
__device__ __forceinline__ ull pk2(float a, float b) {
    ull r;
    asm("mov.b64 %0, {%1, %2};" : "=l"(r) : "f"(a), "f"(b));
    return r;
}
__device__ __forceinline__ void up2(ull v, float& a, float& b) {
    asm("mov.b64 {%0, %1}, %2;" : "=f"(a), "=f"(b) : "l"(v));
}
__device__ __forceinline__ ull fma2(ull a, ull b, ull c) {
    ull d;
    asm("fma.rn.f32x2 %0, %1, %2, %3;" : "=l"(d) : "l"(a), "l"(b), "l"(c));
    return d;
}
__device__ __forceinline__ uint32_t h2(float a, float b) {
    __half2 h = __floats2half2_rn(a, b);   // x(lo)=a, y(hi)=b
    return *(uint32_t*)&h;
}
__device__ __forceinline__ long long load_idx(const void* ell, long long pos,
                                              int is64) {
    if (is64) return ((const long long*)ell)[pos];
    return (long long)((const int*)ell)[pos];
}

// m16n8k16 f16 MMA (row.col), fp32 accumulate in place
__device__ __forceinline__ void hmma16(float d[4], uint32_t a0, uint32_t a1,
                                       uint32_t a2, uint32_t a3,
                                       uint32_t b0, uint32_t b1) {
    asm volatile(
        "mma.sync.aligned.m16n8k16.row.col.f32.f16.f16.f32 "
        "{%0,%1,%2,%3}, {%4,%5,%6,%7}, {%8,%9}, {%0,%1,%2,%3};"
        : "+f"(d[0]), "+f"(d[1]), "+f"(d[2]), "+f"(d[3])
        : "r"(a0), "r"(a1), "r"(a2), "r"(a3), "r"(b0), "r"(b1));
}

// ---------------------------------------------------------------------------
// Kernel 1: tiled layer-1 precompute (32 nodes/block, W1 slice in smem,
// fp16 output). Block 0 thread 0 also detects the edge-index dtype.
// ---------------------------------------------------------------------------
#define NB 32
__global__ void __launch_bounds__(256, 2)
node_precompute(const float* __restrict__ xd,
                const float* __restrict__ xs,
                const float* __restrict__ W1,
                const float* __restrict__ b1,
                const long long* __restrict__ ell,
                int n_drug, int n_dis, int nb_drug) {
    extern __shared__ float nsm[];
    float* w1s  = nsm;              // 100*128
    float* xsh2 = nsm + 12800;      // 100*32, [k][node]

    const int tid = threadIdx.x;
    const int bid = blockIdx.x;

    if (bid == 0 && tid == 0) {
        int ok64 = 1;
#pragma unroll
        for (int t = 0; t < 8; t++) {
            long long v = ell[t];
            if (v < 0 || v >= 1000000) ok64 = 0;
        }
        g_idx64 = ok64;
    }

    const bool is_drug = bid < nb_drug;
    const int  n       = is_drug ? n_drug : n_dis;
    const int  nbase   = (is_drug ? bid : bid - nb_drug) * NB;
    const float* x   = is_drug ? xd : xs;
    const float* w   = W1 + (is_drug ? 0 : 100 * 128);
    __half*      out = is_drug ? g_hd : g_he;

    for (int i = tid; i < 100 * 128; i += 256) w1s[i] = w[i];
    for (int i = tid; i < NB * 100; i += 256) {
        int node = i & (NB - 1);
        int k    = i >> 5;
        int gn   = nbase + node;
        xsh2[k * NB + node] = (gn < n) ? x[(long)gn * 100 + k] : 0.0f;
    }
    __syncthreads();

    const int m = tid & 127;
    const int g = tid >> 7;           // 0..1 -> nodes 16g..16g+15

    float bm = is_drug ? b1[m] : 0.0f;
    ull acc[8];
#pragma unroll
    for (int p = 0; p < 8; p++) acc[p] = pk2(bm, bm);

#pragma unroll 4
    for (int k = 0; k < 100; k++) {
        float wv = w1s[k * 128 + m];
        ull w2 = pk2(wv, wv);
#pragma unroll
        for (int q = 0; q < 4; q++) {
            float4 xa = *(const float4*)&xsh2[k * NB + 16 * g + 4 * q];
            acc[2 * q + 0] = fma2(pk2(xa.x, xa.y), w2, acc[2 * q + 0]);
            acc[2 * q + 1] = fma2(pk2(xa.z, xa.w), w2, acc[2 * q + 1]);
        }
    }

#pragma unroll
    for (int p = 0; p < 8; p++) {
        float a, b;
        up2(acc[p], a, b);
        int n0 = nbase + 16 * g + 2 * p;
        if (n0 < n)     out[(long)n0 * 128 + m]       = __float2half_rn(a);
        if (n0 + 1 < n) out[(long)(n0 + 1) * 128 + m] = __float2half_rn(b);
    }
}

// ---------------------------------------------------------------------------
// Kernel 2: persistent per-edge MLP, warp-autonomous, fp16 tensor path.
// Block = 256 threads (8 warps), tile = 128 edges, warp owns 16 edges.
// smem: per-warp hs (16 rows x 128 fp16, row stride 272B -> conflict-free)
//       + W2 B-fragments (fp16, 8 KB).
// ---------------------------------------------------------------------------
#define EPB   128
#define NTHR  256
#define HS_RS 272                       // bytes per hs row (256 + 16 pad)

__global__ void __launch_bounds__(NTHR, 3)
edge_mlp_kernel(const void* __restrict__ ell,
                const float* __restrict__ W2, const float* __restrict__ b2,
                const float* __restrict__ W3, const float* __restrict__ b3,
                const float* __restrict__ W4, const float* __restrict__ b4,
                float* __restrict__ out, int E, int n_tiles) {
    __shared__ char  hsraw[8 * 16 * HS_RS];   // 34816 B
    __shared__ uint2 wfr[8 * 4 * 32];         // W2 frags: [ks8][nb4][lane] 8 KB

    const int tid  = threadIdx.x;
    const int warp = tid >> 5;
    const int lane = tid & 31;
    const int is64 = g_idx64;

    // ---- stage W2 fp16 B-fragments once ----
    for (int idx = tid; idx < 1024; idx += NTHR) {
        int ln = idx & 31;
        int nb = (idx >> 5) & 3;
        int ks = idx >> 7;
        int n  = 8 * nb + (ln >> 2);
        int kb = 16 * ks + 2 * (ln & 3);
        uint2 b;
        b.x = h2(W2[kb * 32 + n],       W2[(kb + 1) * 32 + n]);
        b.y = h2(W2[(kb + 8) * 32 + n], W2[(kb + 9) * 32 + n]);
        wfr[idx] = b;
    }
    __syncthreads();

    const int g = lane >> 2;        // 0..7
    const int c = lane & 3;         // 0..3

    // ---- register-resident constants ----
    float b2r[4][2];
#pragma unroll
    for (int nb = 0; nb < 4; nb++) {
        b2r[nb][0] = __ldg(&b2[8 * nb + 2 * c + 0]);
        b2r[nb][1] = __ldg(&b2[8 * nb + 2 * c + 1]);
    }
    uint32_t w3f[2][2][2];
#pragma unroll
    for (int ks3 = 0; ks3 < 2; ks3++)
#pragma unroll
        for (int nb3 = 0; nb3 < 2; nb3++) {
            int n  = 8 * nb3 + g;
            int kb = 16 * ks3 + 2 * c;
            w3f[ks3][nb3][0] = h2(__ldg(&W3[kb * 16 + n]),
                                  __ldg(&W3[(kb + 1) * 16 + n]));
            w3f[ks3][nb3][1] = h2(__ldg(&W3[(kb + 8) * 16 + n]),
                                  __ldg(&W3[(kb + 9) * 16 + n]));
        }
    float b3r[2][2], w4r[2][2];
#pragma unroll
    for (int o = 0; o < 2; o++) {
        b3r[o][0] = __ldg(&b3[8 * o + 2 * c + 0]);
        b3r[o][1] = __ldg(&b3[8 * o + 2 * c + 1]);
        w4r[o][0] = __ldg(&W4[8 * o + 2 * c + 0]);
        w4r[o][1] = __ldg(&W4[8 * o + 2 * c + 1]);
    }
    const float b4v = __ldg(&b4[0]);

    char* hw = hsraw + warp * 16 * HS_RS;
    const char* hdb = (const char*)g_hd;
    const char* heb = (const char*)g_he;

    for (int tile = blockIdx.x; tile < n_tiles; tile += gridDim.x) {
        const int ebase = tile * EPB + warp * 16;

        // ---- phase 1: coalesced fp16 gather + fp32 combine + leaky ----
        {
            int e  = ebase + (lane & 15);
            int ec = e < E ? e : (E - 1);
            long long pos = (lane < 16) ? (long long)ec : (long long)E + ec;
            int vi = (int)load_idx(ell, pos, is64);

            const uint32_t loff = (uint32_t)(lane << 3);   // lane*8 bytes

#pragma unroll
            for (int t = 0; t < 16; t++) {
                uint32_t i = (uint32_t)__shfl_sync(0xffffffffu, vi, t);
                uint32_t j = (uint32_t)__shfl_sync(0xffffffffu, vi, 16 + t);
                const uint2 a = *(const uint2*)(hdb + (i << 8) + loff);
                const uint2 b = *(const uint2*)(heb + (j << 8) + loff);
                float2 a0 = __half22float2(*(const __half2*)&a.x);
                float2 a1 = __half22float2(*(const __half2*)&a.y);
                float2 b0 = __half22float2(*(const __half2*)&b.x);
                float2 b1 = __half22float2(*(const __half2*)&b.y);
                uint2 s;
                s.x = h2(lrelu(a0.x + b0.x), lrelu(a0.y + b0.y));
                s.y = h2(lrelu(a1.x + b1.x), lrelu(a1.y + b1.y));
                *(uint2*)(hw + t * HS_RS + (lane << 3)) = s;
            }
        }
        __syncwarp();

        // ---- phase 2: layer-2 mma (8 k16-steps x 4 n-blocks) ----
        float acc[4][4];
#pragma unroll
        for (int nb = 0; nb < 4; nb++)
#pragma unroll
            for (int q = 0; q < 4; q++) acc[nb][q] = 0.0f;

        {
            const char* r0 = hw + g * HS_RS + 4 * c;          // row g
            const char* r1 = r0 + 8 * HS_RS;                  // row g+8
#pragma unroll
            for (int ks = 0; ks < 8; ks++) {
                uint32_t a0 = *(const uint32_t*)(r0 + 32 * ks);
                uint32_t a1 = *(const uint32_t*)(r1 + 32 * ks);
                uint32_t a2 = *(const uint32_t*)(r0 + 32 * ks + 16);
                uint32_t a3 = *(const uint32_t*)(r1 + 32 * ks + 16);
#pragma unroll
                for (int nb = 0; nb < 4; nb++) {
                    uint2 bb = wfr[(ks * 4 + nb) * 32 + lane];
                    hmma16(acc[nb], a0, a1, a2, a3, bb.x, bb.y);
                }
            }
        }
        __syncwarp();    // hs consumed; safe to rewrite next tile

        // ---- phase 3: layer-3 mma — layer-2 D frag IS layer-3 A frag ----
        float acc3[2][4];
#pragma unroll
        for (int o = 0; o < 2; o++)
#pragma unroll
            for (int q = 0; q < 4; q++) acc3[o][q] = 0.0f;

#pragma unroll
        for (int ks3 = 0; ks3 < 2; ks3++) {
            const int nbA = 2 * ks3;
            const int nbB = 2 * ks3 + 1;
            uint32_t a0 = h2(lrelu(acc[nbA][0] + b2r[nbA][0]),
                             lrelu(acc[nbA][1] + b2r[nbA][1]));
            uint32_t a1 = h2(lrelu(acc[nbA][2] + b2r[nbA][0]),
                             lrelu(acc[nbA][3] + b2r[nbA][1]));
            uint32_t a2 = h2(lrelu(acc[nbB][0] + b2r[nbB][0]),
                             lrelu(acc[nbB][1] + b2r[nbB][1]));
            uint32_t a3 = h2(lrelu(acc[nbB][2] + b2r[nbB][0]),
                             lrelu(acc[nbB][3] + b2r[nbB][1]));
#pragma unroll
            for (int nb3 = 0; nb3 < 2; nb3++)
                hmma16(acc3[nb3], a0, a1, a2, a3,
                       w3f[ks3][nb3][0], w3f[ks3][nb3][1]);
        }

        // ---- phase 4: bias+leaky, dot W4, shfl-reduce over c, store ----
        {
            float y0 = 0.0f, y1 = 0.0f;
#pragma unroll
            for (int o = 0; o < 2; o++) {
                y0 = fmaf(lrelu(acc3[o][0] + b3r[o][0]), w4r[o][0], y0);
                y0 = fmaf(lrelu(acc3[o][1] + b3r[o][1]), w4r[o][1], y0);
                y1 = fmaf(lrelu(acc3[o][2] + b3r[o][0]), w4r[o][0], y1);
                y1 = fmaf(lrelu(acc3[o][3] + b3r[o][1]), w4r[o][1], y1);
            }
            y0 += __shfl_xor_sync(0xffffffffu, y0, 1);
            y0 += __shfl_xor_sync(0xffffffffu, y0, 2);
            y1 += __shfl_xor_sync(0xffffffffu, y1, 1);
            y1 += __shfl_xor_sync(0xffffffffu, y1, 2);

            if (c == 0) {
                int e0 = ebase + g;
                if (e0 < E)     out[e0]     = y0 + b4v;
                if (e0 + 8 < E) out[e0 + 8] = y1 + b4v;
            }
        }
    }
}

// ---------------------------------------------------------------------------
extern "C" void kernel_launch(void* const* d_in, const int* in_sizes, int n_in,
                              void* d_out, int out_size) {
    const float* xd  = (const float*)d_in[0];
    const float* xs  = (const float*)d_in[1];
    const void*  ell = d_in[2];
    const float* W1  = (const float*)d_in[3];
    const float* b1  = (const float*)d_in[4];
    const float* W2  = (const float*)d_in[5];
    const float* b2  = (const float*)d_in[6];
    const float* W3  = (const float*)d_in[7];
    const float* b3  = (const float*)d_in[8];
    const float* W4  = (const float*)d_in[9];
    const float* b4  = (const float*)d_in[10];
    float* out = (float*)d_out;

    int n_drug = in_sizes[0] / 100;
    int n_dis  = in_sizes[1] / 100;
    int E      = in_sizes[2] / 2;

    int nb_drug = (n_drug + NB - 1) / NB;
    int nb_dis  = (n_dis  + NB - 1) / NB;
    int node_smem = (12800 + 100 * NB) * 4;
    cudaFuncSetAttribute(node_precompute,
                         cudaFuncAttributeMaxDynamicSharedMemorySize, node_smem);
    node_precompute<<<nb_drug + nb_dis, 256, node_smem>>>(
        xd, xs, W1, b1, (const long long*)ell, n_drug, n_dis, nb_drug);

    int n_tiles = (E + EPB - 1) / EPB;
    int grid = 3 * 148;
    if (grid > n_tiles) grid = n_tiles;
    edge_mlp_kernel<<<grid, NTHR>>>(ell, W2, b2, W3, b3, W4, b4,
                                    out, E, n_tiles);
}

// round 11
// speedup vs baseline: 3.5154x; 1.1462x over previous
#include <cuda_runtime.h>
#include <cuda_bf16.h>
#include <cuda_fp16.h>
#include <cstdint>

// ---------------------------------------------------------------------------
// Classifier: out[e] = MLP(concat(x_drug[i_e], x_disease[j_e]))
// Layer-1 factored per-node (fp32 compute, fp16 storage):
//   h_drug    = x_drug    @ W1[0:100]   + b1     (n_drug x 128)
//   h_disease = x_disease @ W1[100:200]          (n_dis  x 128)
// Per edge: h = lrelu(hd[i]+he[j]) in pure half2 (HADD2/HMUL2/HMAX2) -> fp16
// smem; layer-2 (128->32) and layer-3 (32->16) on mma.m16n8k16.f16 (fp32
// accum) with composing fragment layouts (layer-2 D == layer-3 A);
// layer-4 dot + shfl reduce. Warp-autonomous: no per-tile block syncs.
// ---------------------------------------------------------------------------

typedef unsigned long long ull;

#define MAX_NODES 16384
__device__ __half g_hd[MAX_NODES * 128];
__device__ __half g_he[MAX_NODES * 128];
__device__ int    g_idx64;   // 1 if edge index buffer is int64, 0 if int32

__device__ __forceinline__ float lrelu(float v) {
    return v >= 0.0f ? v : 0.01f * v;
}
__device__ __forceinline__ ull pk2(float a, float b) {
    ull r;
    asm("mov.b64 %0, {%1, %2};" : "=l"(r) : "f"(a), "f"(b));
    return r;
}
__device__ __forceinline__ void up2(ull v, float& a, float& b) {
    asm("mov.b64 {%0, %1}, %2;" : "=f"(a), "=f"(b) : "l"(v));
}
__device__ __forceinline__ ull fma2(ull a, ull b, ull c) {
    ull d;
    asm("fma.rn.f32x2 %0, %1, %2, %3;" : "=l"(d) : "l"(a), "l"(b), "l"(c));
    return d;
}
__device__ __forceinline__ uint32_t h2(float a, float b) {
    __half2 h = __floats2half2_rn(a, b);   // x(lo)=a, y(hi)=b
    return *(uint32_t*)&h;
}
// packed fp16 add + leaky-relu: lrelu(x) == max(x, 0.01*x) elementwise
__device__ __forceinline__ uint32_t haddlrelu2(uint32_t a, uint32_t b,
                                               __half2 c01) {
    __half2 s = __hadd2(*(__half2*)&a, *(__half2*)&b);
    __half2 r = __hmax2(s, __hmul2(s, c01));
    return *(uint32_t*)&r;
}
__device__ __forceinline__ long long load_idx(const void* ell, long long pos,
                                              int is64) {
    if (is64) return ((const long long*)ell)[pos];
    return (long long)((const int*)ell)[pos];
}

// m16n8k16 f16 MMA (row.col), fp32 accumulate in place
__device__ __forceinline__ void hmma16(float d[4], uint32_t a0, uint32_t a1,
                                       uint32_t a2, uint32_t a3,
                                       uint32_t b0, uint32_t b1) {
    asm volatile(
        "mma.sync.aligned.m16n8k16.row.col.f32.f16.f16.f32 "
        "{%0,%1,%2,%3}, {%4,%5,%6,%7}, {%8,%9}, {%0,%1,%2,%3};"
        : "+f"(d[0]), "+f"(d[1]), "+f"(d[2]), "+f"(d[3])
        : "r"(a0), "r"(a1), "r"(a2), "r"(a3), "r"(b0), "r"(b1));
}

// ---------------------------------------------------------------------------
// Kernel 1: tiled layer-1 precompute (32 nodes/block, W1 slice in smem,
// fp16 output). Block 0 thread 0 also detects the edge-index dtype.
// ---------------------------------------------------------------------------
#define NB 32
__global__ void __launch_bounds__(256, 2)
node_precompute(const float* __restrict__ xd,
                const float* __restrict__ xs,
                const float* __restrict__ W1,
                const float* __restrict__ b1,
                const long long* __restrict__ ell,
                int n_drug, int n_dis, int nb_drug) {
    extern __shared__ float nsm[];
    float* w1s  = nsm;              // 100*128
    float* xsh2 = nsm + 12800;      // 100*32, [k][node]

    const int tid = threadIdx.x;
    const int bid = blockIdx.x;

    if (bid == 0 && tid == 0) {
        int ok64 = 1;
#pragma unroll
        for (int t = 0; t < 8; t++) {
            long long v = ell[t];
            if (v < 0 || v >= 1000000) ok64 = 0;
        }
        g_idx64 = ok64;
    }

    const bool is_drug = bid < nb_drug;
    const int  n       = is_drug ? n_drug : n_dis;
    const int  nbase   = (is_drug ? bid : bid - nb_drug) * NB;
    const float* x   = is_drug ? xd : xs;
    const float* w   = W1 + (is_drug ? 0 : 100 * 128);
    __half*      out = is_drug ? g_hd : g_he;

    for (int i = tid; i < 3200; i += 256)
        ((float4*)w1s)[i] = ((const float4*)w)[i];
    // x rows are 400 B (8-aligned): stage via float2
    for (int i = tid; i < NB * 50; i += 256) {
        int node = i & (NB - 1);
        int k2   = i >> 5;           // 0..49
        int gn   = nbase + node;
        float2 v = make_float2(0.0f, 0.0f);
        if (gn < n) v = *(const float2*)&x[(long)gn * 100 + 2 * k2];
        xsh2[(2 * k2) * NB + node]     = v.x;
        xsh2[(2 * k2 + 1) * NB + node] = v.y;
    }
    __syncthreads();

    const int m = tid & 127;
    const int g = tid >> 7;           // 0..1 -> nodes 16g..16g+15

    float bm = is_drug ? b1[m] : 0.0f;
    ull acc[8];
#pragma unroll
    for (int p = 0; p < 8; p++) acc[p] = pk2(bm, bm);

#pragma unroll 4
    for (int k = 0; k < 100; k++) {
        float wv = w1s[k * 128 + m];
        ull w2 = pk2(wv, wv);
#pragma unroll
        for (int q = 0; q < 4; q++) {
            float4 xa = *(const float4*)&xsh2[k * NB + 16 * g + 4 * q];
            acc[2 * q + 0] = fma2(pk2(xa.x, xa.y), w2, acc[2 * q + 0]);
            acc[2 * q + 1] = fma2(pk2(xa.z, xa.w), w2, acc[2 * q + 1]);
        }
    }

#pragma unroll
    for (int p = 0; p < 8; p++) {
        float a, b;
        up2(acc[p], a, b);
        int n0 = nbase + 16 * g + 2 * p;
        if (n0 < n)     out[(long)n0 * 128 + m]       = __float2half_rn(a);
        if (n0 + 1 < n) out[(long)(n0 + 1) * 128 + m] = __float2half_rn(b);
    }
}

// ---------------------------------------------------------------------------
// Kernel 2: persistent per-edge MLP, warp-autonomous, fp16 tensor path.
// Block = 256 threads (8 warps), tile = 128 edges, warp owns 16 edges.
// smem: per-warp hs (16 rows x 128 fp16, stride 272B) + W2 frags (8 KB).
// ---------------------------------------------------------------------------
#define EPB   128
#define NTHR  256
#define HS_RS 272                       // bytes per hs row (256 + 16 pad)

__global__ void __launch_bounds__(NTHR, 3)
edge_mlp_kernel(const void* __restrict__ ell,
                const float* __restrict__ W2, const float* __restrict__ b2,
                const float* __restrict__ W3, const float* __restrict__ b3,
                const float* __restrict__ W4, const float* __restrict__ b4,
                float* __restrict__ out, int E, int n_tiles) {
    __shared__ char  hsraw[8 * 16 * HS_RS];   // 34816 B
    __shared__ uint4 wfr[8 * 2 * 32];         // W2 frags: [ks8][nbp2][lane] 8 KB

    const int tid  = threadIdx.x;
    const int warp = tid >> 5;
    const int lane = tid & 31;
    const int is64 = g_idx64;

    // ---- stage W2 fp16 B-fragments once (nb-paired uint4) ----
    for (int idx = tid; idx < 512; idx += NTHR) {
        int ln  = idx & 31;
        int nbp = (idx >> 5) & 1;
        int ks  = idx >> 6;
        int n0  = 16 * nbp + (ln >> 2);
        int n1  = n0 + 8;
        int kb  = 16 * ks + 2 * (ln & 3);
        uint4 b;
        b.x = h2(W2[kb * 32 + n0],       W2[(kb + 1) * 32 + n0]);
        b.y = h2(W2[(kb + 8) * 32 + n0], W2[(kb + 9) * 32 + n0]);
        b.z = h2(W2[kb * 32 + n1],       W2[(kb + 1) * 32 + n1]);
        b.w = h2(W2[(kb + 8) * 32 + n1], W2[(kb + 9) * 32 + n1]);
        wfr[idx] = b;
    }
    __syncthreads();

    const int g = lane >> 2;        // 0..7
    const int c = lane & 3;         // 0..3

    // ---- register-resident constants ----
    float b2r[4][2];
#pragma unroll
    for (int nb = 0; nb < 4; nb++) {
        b2r[nb][0] = __ldg(&b2[8 * nb + 2 * c + 0]);
        b2r[nb][1] = __ldg(&b2[8 * nb + 2 * c + 1]);
    }
    uint32_t w3f[2][2][2];
#pragma unroll
    for (int ks3 = 0; ks3 < 2; ks3++)
#pragma unroll
        for (int nb3 = 0; nb3 < 2; nb3++) {
            int n  = 8 * nb3 + g;
            int kb = 16 * ks3 + 2 * c;
            w3f[ks3][nb3][0] = h2(__ldg(&W3[kb * 16 + n]),
                                  __ldg(&W3[(kb + 1) * 16 + n]));
            w3f[ks3][nb3][1] = h2(__ldg(&W3[(kb + 8) * 16 + n]),
                                  __ldg(&W3[(kb + 9) * 16 + n]));
        }
    float b3r[2][2], w4r[2][2];
#pragma unroll
    for (int o = 0; o < 2; o++) {
        b3r[o][0] = __ldg(&b3[8 * o + 2 * c + 0]);
        b3r[o][1] = __ldg(&b3[8 * o + 2 * c + 1]);
        w4r[o][0] = __ldg(&W4[8 * o + 2 * c + 0]);
        w4r[o][1] = __ldg(&W4[8 * o + 2 * c + 1]);
    }
    const float b4v = __ldg(&b4[0]);
    const __half2 c01 = __float2half2_rn(0.01f);

    char* hw = hsraw + warp * 16 * HS_RS;
    const char* hdb = (const char*)g_hd;
    const char* heb = (const char*)g_he;

    const int half = lane >> 4;                 // which of the 2 rows/iter
    const int sub  = lane & 15;                 // 16B unit within row
    const uint32_t boff = (uint32_t)(sub << 4);

    for (int tile = blockIdx.x; tile < n_tiles; tile += gridDim.x) {
        const int ebase = tile * EPB + warp * 16;

        // ---- phase 1: gather + half2 combine+lrelu -> fp16 smem ----
        {
            int e  = ebase + (lane & 15);
            int ec = e < E ? e : (E - 1);
            long long pos = (lane < 16) ? (long long)ec : (long long)E + ec;
            int vi = (int)load_idx(ell, pos, is64);

#pragma unroll
            for (int t = 0; t < 8; t++) {
                int r = 2 * t + half;
                uint32_t i = (uint32_t)__shfl_sync(0xffffffffu, vi, r);
                uint32_t j = (uint32_t)__shfl_sync(0xffffffffu, vi, r + 16);
                const uint4 a = *(const uint4*)(hdb + (i << 8) + boff);
                const uint4 b = *(const uint4*)(heb + (j << 8) + boff);
                uint4 s;
                s.x = haddlrelu2(a.x, b.x, c01);
                s.y = haddlrelu2(a.y, b.y, c01);
                s.z = haddlrelu2(a.z, b.z, c01);
                s.w = haddlrelu2(a.w, b.w, c01);
                *(uint4*)(hw + r * HS_RS + boff) = s;
            }
        }
        __syncwarp();

        // ---- phase 2: layer-2 mma (8 k16-steps x 2 nb-pairs) ----
        float acc[4][4];
#pragma unroll
        for (int nb = 0; nb < 4; nb++)
#pragma unroll
            for (int q = 0; q < 4; q++) acc[nb][q] = 0.0f;

        {
            const char* r0 = hw + g * HS_RS + 4 * c;          // row g
            const char* r1 = r0 + 8 * HS_RS;                  // row g+8
#pragma unroll
            for (int ks = 0; ks < 8; ks++) {
                uint32_t a0 = *(const uint32_t*)(r0 + 32 * ks);
                uint32_t a1 = *(const uint32_t*)(r1 + 32 * ks);
                uint32_t a2 = *(const uint32_t*)(r0 + 32 * ks + 16);
                uint32_t a3 = *(const uint32_t*)(r1 + 32 * ks + 16);
#pragma unroll
                for (int nbp = 0; nbp < 2; nbp++) {
                    uint4 bb = wfr[(ks * 2 + nbp) * 32 + lane];
                    hmma16(acc[2 * nbp],     a0, a1, a2, a3, bb.x, bb.y);
                    hmma16(acc[2 * nbp + 1], a0, a1, a2, a3, bb.z, bb.w);
                }
            }
        }
        __syncwarp();    // hs consumed; safe to rewrite next tile

        // ---- phase 3: layer-3 mma — layer-2 D frag IS layer-3 A frag ----
        float acc3[2][4];
#pragma unroll
        for (int o = 0; o < 2; o++)
#pragma unroll
            for (int q = 0; q < 4; q++) acc3[o][q] = 0.0f;

#pragma unroll
        for (int ks3 = 0; ks3 < 2; ks3++) {
            const int nbA = 2 * ks3;
            const int nbB = 2 * ks3 + 1;
            uint32_t a0 = h2(lrelu(acc[nbA][0] + b2r[nbA][0]),
                             lrelu(acc[nbA][1] + b2r[nbA][1]));
            uint32_t a1 = h2(lrelu(acc[nbA][2] + b2r[nbA][0]),
                             lrelu(acc[nbA][3] + b2r[nbA][1]));
            uint32_t a2 = h2(lrelu(acc[nbB][0] + b2r[nbB][0]),
                             lrelu(acc[nbB][1] + b2r[nbB][1]));
            uint32_t a3 = h2(lrelu(acc[nbB][2] + b2r[nbB][0]),
                             lrelu(acc[nbB][3] + b2r[nbB][1]));
#pragma unroll
            for (int nb3 = 0; nb3 < 2; nb3++)
                hmma16(acc3[nb3], a0, a1, a2, a3,
                       w3f[ks3][nb3][0], w3f[ks3][nb3][1]);
        }

        // ---- phase 4: bias+leaky, dot W4, shfl-reduce over c, store ----
        {
            float y0 = 0.0f, y1 = 0.0f;
#pragma unroll
            for (int o = 0; o < 2; o++) {
                y0 = fmaf(lrelu(acc3[o][0] + b3r[o][0]), w4r[o][0], y0);
                y0 = fmaf(lrelu(acc3[o][1] + b3r[o][1]), w4r[o][1], y0);
                y1 = fmaf(lrelu(acc3[o][2] + b3r[o][0]), w4r[o][0], y1);
                y1 = fmaf(lrelu(acc3[o][3] + b3r[o][1]), w4r[o][1], y1);
            }
            y0 += __shfl_xor_sync(0xffffffffu, y0, 1);
            y0 += __shfl_xor_sync(0xffffffffu, y0, 2);
            y1 += __shfl_xor_sync(0xffffffffu, y1, 1);
            y1 += __shfl_xor_sync(0xffffffffu, y1, 2);

            if (c == 0) {
                int e0 = ebase + g;
                if (e0 < E)     out[e0]     = y0 + b4v;
                if (e0 + 8 < E) out[e0 + 8] = y1 + b4v;
            }
        }
    }
}

// ---------------------------------------------------------------------------
extern "C" void kernel_launch(void* const* d_in, const int* in_sizes, int n_in,
                              void* d_out, int out_size) {
    const float* xd  = (const float*)d_in[0];
    const float* xs  = (const float*)d_in[1];
    const void*  ell = d_in[2];
    const float* W1  = (const float*)d_in[3];
    const float* b1  = (const float*)d_in[4];
    const float* W2  = (const float*)d_in[5];
    const float* b2  = (const float*)d_in[6];
    const float* W3  = (const float*)d_in[7];
    const float* b3  = (const float*)d_in[8];
    const float* W4  = (const float*)d_in[9];
    const float* b4  = (const float*)d_in[10];
    float* out = (float*)d_out;

    int n_drug = in_sizes[0] / 100;
    int n_dis  = in_sizes[1] / 100;
    int E      = in_sizes[2] / 2;

    int nb_drug = (n_drug + NB - 1) / NB;
    int nb_dis  = (n_dis  + NB - 1) / NB;
    int node_smem = (12800 + 100 * NB) * 4;
    cudaFuncSetAttribute(node_precompute,
                         cudaFuncAttributeMaxDynamicSharedMemorySize, node_smem);
    node_precompute<<<nb_drug + nb_dis, 256, node_smem>>>(
        xd, xs, W1, b1, (const long long*)ell, n_drug, n_dis, nb_drug);

    int n_tiles = (E + EPB - 1) / EPB;
    int grid = 3 * 148;
    if (grid > n_tiles) grid = n_tiles;
    edge_mlp_kernel<<<grid, NTHR>>>(ell, W2, b2, W3, b3, W4, b4,
                                    out, E, n_tiles);
}

// round 12
// speedup vs baseline: 3.7679x; 1.0718x over previous
#include <cuda_runtime.h>
#include <cuda_bf16.h>
#include <cuda_fp16.h>
#include <cstdint>

// ---------------------------------------------------------------------------
// Classifier: out[e] = MLP(concat(x_drug[i_e], x_disease[j_e]))
// Layer-1 factored per-node, computed on tensor cores with hi/lo fp16 split
// (x = xh+xl, W1 = Wh+Wl; acc = xh@Wh + xl@Wh + xh@Wl in fp32 -> error ~1e-7):
//   h_drug    = x_drug    @ W1[0:100]   + b1     (n_drug x 128, fp16 tables)
//   h_disease = x_disease @ W1[100:200]          (n_dis  x 128)
// Per edge: h = lrelu(hd[i]+he[j]) in half2 -> fp16 smem; layer-2 (128->32)
// and layer-3 (32->16) on mma.m16n8k16.f16 (fp32 accum) with composing
// fragment layouts; layer-4 dot + shfl reduce. Warp-autonomous.
// ---------------------------------------------------------------------------

typedef unsigned long long ull;

#define MAX_NODES 16384
__device__ __half g_hd[MAX_NODES * 128];
__device__ __half g_he[MAX_NODES * 128];
__device__ int    g_idx64;   // 1 if edge index buffer is int64, 0 if int32

__device__ __forceinline__ float lrelu(float v) {
    return v >= 0.0f ? v : 0.01f * v;
}
__device__ __forceinline__ uint32_t h2(float a, float b) {
    __half2 h = __floats2half2_rn(a, b);   // x(lo)=a, y(hi)=b
    return *(uint32_t*)&h;
}
// packed fp16 add + leaky-relu: lrelu(x) == max(x, 0.01*x) elementwise
__device__ __forceinline__ uint32_t haddlrelu2(uint32_t a, uint32_t b,
                                               __half2 c01) {
    __half2 s = __hadd2(*(__half2*)&a, *(__half2*)&b);
    __half2 r = __hmax2(s, __hmul2(s, c01));
    return *(uint32_t*)&r;
}
__device__ __forceinline__ long long load_idx(const void* ell, long long pos,
                                              int is64) {
    if (is64) return ((const long long*)ell)[pos];
    return (long long)((const int*)ell)[pos];
}

// m16n8k16 f16 MMA (row.col), fp32 accumulate in place
__device__ __forceinline__ void hmma16(float d[4], uint32_t a0, uint32_t a1,
                                       uint32_t a2, uint32_t a3,
                                       uint32_t b0, uint32_t b1) {
    asm volatile(
        "mma.sync.aligned.m16n8k16.row.col.f32.f16.f16.f32 "
        "{%0,%1,%2,%3}, {%4,%5,%6,%7}, {%8,%9}, {%0,%1,%2,%3};"
        : "+f"(d[0]), "+f"(d[1]), "+f"(d[2]), "+f"(d[3])
        : "r"(a0), "r"(a1), "r"(a2), "r"(a3), "r"(b0), "r"(b1));
}

// ---------------------------------------------------------------------------
// Kernel 1: layer-1 precompute on tensor cores. 64 nodes/block, 256 threads.
// K = 100 padded to 112 (7 k16-steps). Split-precision: 3 mma passes.
// smem: xh/xl (64 x 112 fp16, row stride 240B) + Wh/Wl frag arrays.
// Block 0 thread 0 also detects the edge-index dtype (JAX w/o x64 -> int32).
// ---------------------------------------------------------------------------
#define NNB   64
#define XS_RS 240                              // 112 halves = 224B + 16 pad
#define NOFF_XH 0
#define NOFF_XL (NOFF_XH + NNB * XS_RS)        // 15360
#define NOFF_WH (NOFF_XL + NNB * XS_RS)        // 30720
#define NOFF_WL (NOFF_WH + 7 * 16 * 32 * 8)    // 59392
#define NSMEM   (NOFF_WL + 7 * 16 * 32 * 8)    // 88064

__global__ void __launch_bounds__(256, 2)
node_precompute(const float* __restrict__ xd,
                const float* __restrict__ xs,
                const float* __restrict__ W1,
                const float* __restrict__ b1,
                const long long* __restrict__ ell,
                int n_drug, int n_dis, int nb_drug) {
    extern __shared__ char nsm[];
    char*  xh  = nsm + NOFF_XH;
    char*  xl  = nsm + NOFF_XL;
    uint2* whf = (uint2*)(nsm + NOFF_WH);
    uint2* wlf = (uint2*)(nsm + NOFF_WL);

    const int tid = threadIdx.x;
    const int bid = blockIdx.x;

    if (bid == 0 && tid == 0) {
        int ok64 = 1;
#pragma unroll
        for (int t = 0; t < 8; t++) {
            long long v = ell[t];
            if (v < 0 || v >= 1000000) ok64 = 0;
        }
        g_idx64 = ok64;
    }

    const bool is_drug = bid < nb_drug;
    const int  n       = is_drug ? n_drug : n_dis;
    const int  nbase   = (is_drug ? bid : bid - nb_drug) * NNB;
    const float* x   = is_drug ? xd : xs;
    const float* w   = W1 + (is_drug ? 0 : 100 * 128);
    __half*      out = is_drug ? g_hd : g_he;

    // ---- stage x hi/lo: 64 rows x 56 u32 (112 halves) ----
    for (int i = tid; i < NNB * 56; i += 256) {
        int row = i / 56;
        int p   = i - row * 56;
        int gn  = nbase + row;
        int k0  = 2 * p;
        float v0 = 0.0f, v1 = 0.0f;
        if (gn < n) {
            if (k0 < 100)     v0 = x[(long)gn * 100 + k0];
            if (k0 + 1 < 100) v1 = x[(long)gn * 100 + k0 + 1];
        }
        float h0 = __half2float(__float2half_rn(v0));
        float h1 = __half2float(__float2half_rn(v1));
        *(uint32_t*)(xh + row * XS_RS + 4 * p) = h2(v0, v1);
        *(uint32_t*)(xl + row * XS_RS + 4 * p) = h2(v0 - h0, v1 - h1);
    }

    // ---- stage W1 hi/lo B-fragments: [7 ks][16 nb][32 lane] uint2 ----
    for (int i = tid; i < 7 * 16 * 32; i += 256) {
        int ln = i & 31;
        int nb = (i >> 5) & 15;
        int ks = i >> 9;
        int nn = 8 * nb + (ln >> 2);
        int kb = 16 * ks + 2 * (ln & 3);
        float f[4];
#pragma unroll
        for (int q = 0; q < 4; q++) {
            int k = kb + (q >> 1) * 8 + (q & 1);
            f[q] = (k < 100) ? w[k * 128 + nn] : 0.0f;
        }
        float fh[4];
#pragma unroll
        for (int q = 0; q < 4; q++) fh[q] = __half2float(__float2half_rn(f[q]));
        whf[i] = make_uint2(h2(f[0], f[1]), h2(f[2], f[3]));
        wlf[i] = make_uint2(h2(f[0] - fh[0], f[1] - fh[1]),
                            h2(f[2] - fh[2], f[3] - fh[3]));
    }
    __syncthreads();

    // ---- mma: warp -> (m-tile mt = warp&3, n-half nh = warp>>2) ----
    const int warp = tid >> 5;
    const int lane = tid & 31;
    const int g = lane >> 2;
    const int c = lane & 3;
    const int mt = warp & 3;
    const int nh = warp >> 2;

    const char* axh = xh + (mt * 16 + g) * XS_RS + 4 * c;
    const char* axl = xl + (mt * 16 + g) * XS_RS + 4 * c;

    float acc[8][4];
#pragma unroll
    for (int nb = 0; nb < 8; nb++)
#pragma unroll
        for (int q = 0; q < 4; q++) acc[nb][q] = 0.0f;

#pragma unroll
    for (int ks = 0; ks < 7; ks++) {
        uint32_t ah0 = *(const uint32_t*)(axh + 32 * ks);
        uint32_t ah1 = *(const uint32_t*)(axh + 32 * ks + 8 * XS_RS);
        uint32_t ah2 = *(const uint32_t*)(axh + 32 * ks + 16);
        uint32_t ah3 = *(const uint32_t*)(axh + 32 * ks + 8 * XS_RS + 16);
        uint32_t al0 = *(const uint32_t*)(axl + 32 * ks);
        uint32_t al1 = *(const uint32_t*)(axl + 32 * ks + 8 * XS_RS);
        uint32_t al2 = *(const uint32_t*)(axl + 32 * ks + 16);
        uint32_t al3 = *(const uint32_t*)(axl + 32 * ks + 8 * XS_RS + 16);
#pragma unroll
        for (int nb = 0; nb < 8; nb++) {
            int fi = (ks * 16 + nh * 8 + nb) * 32 + lane;
            uint2 bh = whf[fi];
            uint2 bl = wlf[fi];
            hmma16(acc[nb], ah0, ah1, ah2, ah3, bh.x, bh.y);
            hmma16(acc[nb], al0, al1, al2, al3, bh.x, bh.y);
            hmma16(acc[nb], ah0, ah1, ah2, ah3, bl.x, bl.y);
        }
    }

    // ---- epilogue: +b1 (drug only), pack fp16 pairs, store ----
    int r0 = nbase + mt * 16 + g;
    int r1 = r0 + 8;
#pragma unroll
    for (int nb = 0; nb < 8; nb++) {
        int col = nh * 64 + nb * 8 + 2 * c;
        float bb0 = is_drug ? __ldg(&b1[col])     : 0.0f;
        float bb1 = is_drug ? __ldg(&b1[col + 1]) : 0.0f;
        if (r0 < n)
            *(uint32_t*)((char*)out + (long)r0 * 256 + col * 2) =
                h2(acc[nb][0] + bb0, acc[nb][1] + bb1);
        if (r1 < n)
            *(uint32_t*)((char*)out + (long)r1 * 256 + col * 2) =
                h2(acc[nb][2] + bb0, acc[nb][3] + bb1);
    }
}

// ---------------------------------------------------------------------------
// Kernel 2: persistent per-edge MLP (unchanged from R11 winner).
// ---------------------------------------------------------------------------
#define EPB   128
#define NTHR  256
#define HS_RS 272                       // bytes per hs row (256 + 16 pad)

__global__ void __launch_bounds__(NTHR, 3)
edge_mlp_kernel(const void* __restrict__ ell,
                const float* __restrict__ W2, const float* __restrict__ b2,
                const float* __restrict__ W3, const float* __restrict__ b3,
                const float* __restrict__ W4, const float* __restrict__ b4,
                float* __restrict__ out, int E, int n_tiles) {
    __shared__ char  hsraw[8 * 16 * HS_RS];   // 34816 B
    __shared__ uint4 wfr[8 * 2 * 32];         // W2 frags: [ks8][nbp2][lane]

    const int tid  = threadIdx.x;
    const int warp = tid >> 5;
    const int lane = tid & 31;
    const int is64 = g_idx64;

    for (int idx = tid; idx < 512; idx += NTHR) {
        int ln  = idx & 31;
        int nbp = (idx >> 5) & 1;
        int ks  = idx >> 6;
        int n0  = 16 * nbp + (ln >> 2);
        int n1  = n0 + 8;
        int kb  = 16 * ks + 2 * (ln & 3);
        uint4 b;
        b.x = h2(W2[kb * 32 + n0],       W2[(kb + 1) * 32 + n0]);
        b.y = h2(W2[(kb + 8) * 32 + n0], W2[(kb + 9) * 32 + n0]);
        b.z = h2(W2[kb * 32 + n1],       W2[(kb + 1) * 32 + n1]);
        b.w = h2(W2[(kb + 8) * 32 + n1], W2[(kb + 9) * 32 + n1]);
        wfr[idx] = b;
    }
    __syncthreads();

    const int g = lane >> 2;
    const int c = lane & 3;

    float b2r[4][2];
#pragma unroll
    for (int nb = 0; nb < 4; nb++) {
        b2r[nb][0] = __ldg(&b2[8 * nb + 2 * c + 0]);
        b2r[nb][1] = __ldg(&b2[8 * nb + 2 * c + 1]);
    }
    uint32_t w3f[2][2][2];
#pragma unroll
    for (int ks3 = 0; ks3 < 2; ks3++)
#pragma unroll
        for (int nb3 = 0; nb3 < 2; nb3++) {
            int n  = 8 * nb3 + g;
            int kb = 16 * ks3 + 2 * c;
            w3f[ks3][nb3][0] = h2(__ldg(&W3[kb * 16 + n]),
                                  __ldg(&W3[(kb + 1) * 16 + n]));
            w3f[ks3][nb3][1] = h2(__ldg(&W3[(kb + 8) * 16 + n]),
                                  __ldg(&W3[(kb + 9) * 16 + n]));
        }
    float b3r[2][2], w4r[2][2];
#pragma unroll
    for (int o = 0; o < 2; o++) {
        b3r[o][0] = __ldg(&b3[8 * o + 2 * c + 0]);
        b3r[o][1] = __ldg(&b3[8 * o + 2 * c + 1]);
        w4r[o][0] = __ldg(&W4[8 * o + 2 * c + 0]);
        w4r[o][1] = __ldg(&W4[8 * o + 2 * c + 1]);
    }
    const float b4v = __ldg(&b4[0]);
    const __half2 c01 = __float2half2_rn(0.01f);

    char* hw = hsraw + warp * 16 * HS_RS;
    const char* hdb = (const char*)g_hd;
    const char* heb = (const char*)g_he;

    const int half = lane >> 4;
    const int sub  = lane & 15;
    const uint32_t boff = (uint32_t)(sub << 4);

    for (int tile = blockIdx.x; tile < n_tiles; tile += gridDim.x) {
        const int ebase = tile * EPB + warp * 16;

        {
            int e  = ebase + (lane & 15);
            int ec = e < E ? e : (E - 1);
            long long pos = (lane < 16) ? (long long)ec : (long long)E + ec;
            int vi = (int)load_idx(ell, pos, is64);

#pragma unroll
            for (int t = 0; t < 8; t++) {
                int r = 2 * t + half;
                uint32_t i = (uint32_t)__shfl_sync(0xffffffffu, vi, r);
                uint32_t j = (uint32_t)__shfl_sync(0xffffffffu, vi, r + 16);
                const uint4 a = *(const uint4*)(hdb + (i << 8) + boff);
                const uint4 b = *(const uint4*)(heb + (j << 8) + boff);
                uint4 s;
                s.x = haddlrelu2(a.x, b.x, c01);
                s.y = haddlrelu2(a.y, b.y, c01);
                s.z = haddlrelu2(a.z, b.z, c01);
                s.w = haddlrelu2(a.w, b.w, c01);
                *(uint4*)(hw + r * HS_RS + boff) = s;
            }
        }
        __syncwarp();

        float acc[4][4];
#pragma unroll
        for (int nb = 0; nb < 4; nb++)
#pragma unroll
            for (int q = 0; q < 4; q++) acc[nb][q] = 0.0f;

        {
            const char* r0 = hw + g * HS_RS + 4 * c;
            const char* r1 = r0 + 8 * HS_RS;
#pragma unroll
            for (int ks = 0; ks < 8; ks++) {
                uint32_t a0 = *(const uint32_t*)(r0 + 32 * ks);
                uint32_t a1 = *(const uint32_t*)(r1 + 32 * ks);
                uint32_t a2 = *(const uint32_t*)(r0 + 32 * ks + 16);
                uint32_t a3 = *(const uint32_t*)(r1 + 32 * ks + 16);
#pragma unroll
                for (int nbp = 0; nbp < 2; nbp++) {
                    uint4 bb = wfr[(ks * 2 + nbp) * 32 + lane];
                    hmma16(acc[2 * nbp],     a0, a1, a2, a3, bb.x, bb.y);
                    hmma16(acc[2 * nbp + 1], a0, a1, a2, a3, bb.z, bb.w);
                }
            }
        }
        __syncwarp();

        float acc3[2][4];
#pragma unroll
        for (int o = 0; o < 2; o++)
#pragma unroll
            for (int q = 0; q < 4; q++) acc3[o][q] = 0.0f;

#pragma unroll
        for (int ks3 = 0; ks3 < 2; ks3++) {
            const int nbA = 2 * ks3;
            const int nbB = 2 * ks3 + 1;
            uint32_t a0 = h2(lrelu(acc[nbA][0] + b2r[nbA][0]),
                             lrelu(acc[nbA][1] + b2r[nbA][1]));
            uint32_t a1 = h2(lrelu(acc[nbA][2] + b2r[nbA][0]),
                             lrelu(acc[nbA][3] + b2r[nbA][1]));
            uint32_t a2 = h2(lrelu(acc[nbB][0] + b2r[nbB][0]),
                             lrelu(acc[nbB][1] + b2r[nbB][1]));
            uint32_t a3 = h2(lrelu(acc[nbB][2] + b2r[nbB][0]),
                             lrelu(acc[nbB][3] + b2r[nbB][1]));
#pragma unroll
            for (int nb3 = 0; nb3 < 2; nb3++)
                hmma16(acc3[nb3], a0, a1, a2, a3,
                       w3f[ks3][nb3][0], w3f[ks3][nb3][1]);
        }

        {
            float y0 = 0.0f, y1 = 0.0f;
#pragma unroll
            for (int o = 0; o < 2; o++) {
                y0 = fmaf(lrelu(acc3[o][0] + b3r[o][0]), w4r[o][0], y0);
                y0 = fmaf(lrelu(acc3[o][1] + b3r[o][1]), w4r[o][1], y0);
                y1 = fmaf(lrelu(acc3[o][2] + b3r[o][0]), w4r[o][0], y1);
                y1 = fmaf(lrelu(acc3[o][3] + b3r[o][1]), w4r[o][1], y1);
            }
            y0 += __shfl_xor_sync(0xffffffffu, y0, 1);
            y0 += __shfl_xor_sync(0xffffffffu, y0, 2);
            y1 += __shfl_xor_sync(0xffffffffu, y1, 1);
            y1 += __shfl_xor_sync(0xffffffffu, y1, 2);

            if (c == 0) {
                int e0 = ebase + g;
                if (e0 < E)     out[e0]     = y0 + b4v;
                if (e0 + 8 < E) out[e0 + 8] = y1 + b4v;
            }
        }
    }
}

// ---------------------------------------------------------------------------
extern "C" void kernel_launch(void* const* d_in, const int* in_sizes, int n_in,
                              void* d_out, int out_size) {
    const float* xd  = (const float*)d_in[0];
    const float* xs  = (const float*)d_in[1];
    const void*  ell = d_in[2];
    const float* W1  = (const float*)d_in[3];
    const float* b1  = (const float*)d_in[4];
    const float* W2  = (const float*)d_in[5];
    const float* b2  = (const float*)d_in[6];
    const float* W3  = (const float*)d_in[7];
    const float* b3  = (const float*)d_in[8];
    const float* W4  = (const float*)d_in[9];
    const float* b4  = (const float*)d_in[10];
    float* out = (float*)d_out;

    int n_drug = in_sizes[0] / 100;
    int n_dis  = in_sizes[1] / 100;
    int E      = in_sizes[2] / 2;

    int nb_drug = (n_drug + NNB - 1) / NNB;
    int nb_dis  = (n_dis  + NNB - 1) / NNB;
    cudaFuncSetAttribute(node_precompute,
                         cudaFuncAttributeMaxDynamicSharedMemorySize, NSMEM);
    node_precompute<<<nb_drug + nb_dis, 256, NSMEM>>>(
        xd, xs, W1, b1, (const long long*)ell, n_drug, n_dis, nb_drug);

    int n_tiles = (E + EPB - 1) / EPB;
    int grid = 3 * 148;
    if (grid > n_tiles) grid = n_tiles;
    edge_mlp_kernel<<<grid, NTHR>>>(ell, W2, b2, W3, b3, W4, b4,
                                    out, E, n_tiles);
}

// round 13
// speedup vs baseline: 4.0046x; 1.0628x over previous
#include <cuda_runtime.h>
#include <cuda_bf16.h>
#include <cuda_fp16.h>
#include <cstdint>

// ---------------------------------------------------------------------------
// Classifier: out[e] = MLP(concat(x_drug[i_e], x_disease[j_e]))
// Layer-1 factored per-node, computed on tensor cores with hi/lo fp16 split
// (x = xh+xl, W1 = Wh+Wl; acc = xh@Wh + xl@Wh + xh@Wl in fp32 -> err ~1e-7):
//   h_drug    = x_drug    @ W1[0:100]   + b1     (n_drug x 128, fp16 tables)
//   h_disease = x_disease @ W1[100:200]          (n_dis  x 128)
// W1 fragments are built ONCE (prep kernel) into fragment-linear global
// tables; node blocks read them coalesced. Per edge: h = lrelu(hd[i]+he[j])
// in half2 -> fp16 smem; layers 2/3 on mma.m16n8k16.f16 (fp32 accum) with
// composing fragment layouts; layer-4 dot + shfl reduce. Warp-autonomous.
// ---------------------------------------------------------------------------

typedef unsigned long long ull;

#define MAX_NODES 16384
__device__ __half g_hd[MAX_NODES * 128];
__device__ __half g_he[MAX_NODES * 128];
__device__ int    g_idx64;   // 1 if edge index buffer is int64, 0 if int32

#define NFRAG (7 * 16 * 32)              // 3584 uint2 per set
__device__ uint2 g_whf[2][NFRAG];        // [0]=drug slice, [1]=disease slice
__device__ uint2 g_wlf[2][NFRAG];

__device__ __forceinline__ float lrelu(float v) {
    return v >= 0.0f ? v : 0.01f * v;
}
__device__ __forceinline__ uint32_t h2(float a, float b) {
    __half2 h = __floats2half2_rn(a, b);   // x(lo)=a, y(hi)=b
    return *(uint32_t*)&h;
}
// packed fp16 add + leaky-relu: lrelu(x) == max(x, 0.01*x) elementwise
__device__ __forceinline__ uint32_t haddlrelu2(uint32_t a, uint32_t b,
                                               __half2 c01) {
    __half2 s = __hadd2(*(__half2*)&a, *(__half2*)&b);
    __half2 r = __hmax2(s, __hmul2(s, c01));
    return *(uint32_t*)&r;
}
__device__ __forceinline__ long long load_idx(const void* ell, long long pos,
                                              int is64) {
    if (is64) return ((const long long*)ell)[pos];
    return (long long)((const int*)ell)[pos];
}

// m16n8k16 f16 MMA (row.col), fp32 accumulate in place
__device__ __forceinline__ void hmma16(float d[4], uint32_t a0, uint32_t a1,
                                       uint32_t a2, uint32_t a3,
                                       uint32_t b0, uint32_t b1) {
    asm volatile(
        "mma.sync.aligned.m16n8k16.row.col.f32.f16.f16.f32 "
        "{%0,%1,%2,%3}, {%4,%5,%6,%7}, {%8,%9}, {%0,%1,%2,%3};"
        : "+f"(d[0]), "+f"(d[1]), "+f"(d[2]), "+f"(d[3])
        : "r"(a0), "r"(a1), "r"(a2), "r"(a3), "r"(b0), "r"(b1));
}

// ---------------------------------------------------------------------------
// Kernel 0: one-time W1 hi/lo fragment build (scattered reads happen ONCE).
// grid = 2 blocks (0: drug slice W1[0:100], 1: disease slice W1[100:200]).
// Also detects the edge-index dtype (JAX w/o x64 -> int32).
// ---------------------------------------------------------------------------
__global__ void w1_frag_prep(const float* __restrict__ W1,
                             const long long* __restrict__ ell) {
    const int sel = blockIdx.x;
    const float* w = W1 + sel * 100 * 128;
    const int tid = threadIdx.x;

    if (sel == 0 && tid == 0) {
        int ok64 = 1;
#pragma unroll
        for (int t = 0; t < 8; t++) {
            long long v = ell[t];
            if (v < 0 || v >= 1000000) ok64 = 0;
        }
        g_idx64 = ok64;
    }

    for (int i = tid; i < NFRAG; i += 256) {
        int ln = i & 31;
        int nb = (i >> 5) & 15;
        int ks = i >> 9;
        int nn = 8 * nb + (ln >> 2);
        int kb = 16 * ks + 2 * (ln & 3);
        float f[4], fh[4];
#pragma unroll
        for (int q = 0; q < 4; q++) {
            int k = kb + (q >> 1) * 8 + (q & 1);
            f[q]  = (k < 100) ? w[k * 128 + nn] : 0.0f;
            fh[q] = __half2float(__float2half_rn(f[q]));
        }
        g_whf[sel][i] = make_uint2(h2(f[0], f[1]), h2(f[2], f[3]));
        g_wlf[sel][i] = make_uint2(h2(f[0] - fh[0], f[1] - fh[1]),
                                   h2(f[2] - fh[2], f[3] - fh[3]));
    }
}

// ---------------------------------------------------------------------------
// Kernel 1: layer-1 precompute on tensor cores. 64 nodes/block, 256 threads.
// K = 100 padded to 112 (7 k16-steps). Split-precision: 3 mma passes.
// smem: xh/xl only (30 KB); W1 frags read coalesced from global (L2-hot).
// ---------------------------------------------------------------------------
#define NNB   64
#define XS_RS 240                              // 112 halves = 224B + 16 pad

__global__ void __launch_bounds__(256, 4)
node_precompute(const float* __restrict__ xd,
                const float* __restrict__ xs,
                const float* __restrict__ b1,
                int n_drug, int n_dis, int nb_drug) {
    __shared__ char xh[NNB * XS_RS];
    __shared__ char xl[NNB * XS_RS];

    const int tid = threadIdx.x;
    const int bid = blockIdx.x;

    const bool is_drug = bid < nb_drug;
    const int  sel     = is_drug ? 0 : 1;
    const int  n       = is_drug ? n_drug : n_dis;
    const int  nbase   = (is_drug ? bid : bid - nb_drug) * NNB;
    const float* x   = is_drug ? xd : xs;
    __half*      out = is_drug ? g_hd : g_he;

    // ---- stage x hi/lo: 64 rows x 56 u32 (112 halves) ----
    for (int i = tid; i < NNB * 56; i += 256) {
        int row = i / 56;
        int p   = i - row * 56;
        int gn  = nbase + row;
        int k0  = 2 * p;
        float v0 = 0.0f, v1 = 0.0f;
        if (gn < n) {
            if (k0 < 100)     v0 = x[(long)gn * 100 + k0];
            if (k0 + 1 < 100) v1 = x[(long)gn * 100 + k0 + 1];
        }
        float h0 = __half2float(__float2half_rn(v0));
        float h1 = __half2float(__float2half_rn(v1));
        *(uint32_t*)(xh + row * XS_RS + 4 * p) = h2(v0, v1);
        *(uint32_t*)(xl + row * XS_RS + 4 * p) = h2(v0 - h0, v1 - h1);
    }
    __syncthreads();

    // ---- mma: warp -> (m-tile mt = warp&3, n-half nh = warp>>2) ----
    const int warp = tid >> 5;
    const int lane = tid & 31;
    const int g = lane >> 2;
    const int c = lane & 3;
    const int mt = warp & 3;
    const int nh = warp >> 2;

    const char* axh = xh + (mt * 16 + g) * XS_RS + 4 * c;
    const char* axl = xl + (mt * 16 + g) * XS_RS + 4 * c;
    const uint2* whf = g_whf[sel];
    const uint2* wlf = g_wlf[sel];

    float acc[8][4];
#pragma unroll
    for (int nb = 0; nb < 8; nb++)
#pragma unroll
        for (int q = 0; q < 4; q++) acc[nb][q] = 0.0f;

#pragma unroll
    for (int ks = 0; ks < 7; ks++) {
        uint32_t ah0 = *(const uint32_t*)(axh + 32 * ks);
        uint32_t ah1 = *(const uint32_t*)(axh + 32 * ks + 8 * XS_RS);
        uint32_t ah2 = *(const uint32_t*)(axh + 32 * ks + 16);
        uint32_t ah3 = *(const uint32_t*)(axh + 32 * ks + 8 * XS_RS + 16);
        uint32_t al0 = *(const uint32_t*)(axl + 32 * ks);
        uint32_t al1 = *(const uint32_t*)(axl + 32 * ks + 8 * XS_RS);
        uint32_t al2 = *(const uint32_t*)(axl + 32 * ks + 16);
        uint32_t al3 = *(const uint32_t*)(axl + 32 * ks + 8 * XS_RS + 16);
#pragma unroll
        for (int nb = 0; nb < 8; nb++) {
            int fi = (ks * 16 + nh * 8 + nb) * 32 + lane;
            uint2 bh = __ldg(&whf[fi]);
            uint2 bl = __ldg(&wlf[fi]);
            hmma16(acc[nb], ah0, ah1, ah2, ah3, bh.x, bh.y);
            hmma16(acc[nb], al0, al1, al2, al3, bh.x, bh.y);
            hmma16(acc[nb], ah0, ah1, ah2, ah3, bl.x, bl.y);
        }
    }

    // ---- epilogue: +b1 (drug only), pack fp16 pairs, store ----
    int r0 = nbase + mt * 16 + g;
    int r1 = r0 + 8;
#pragma unroll
    for (int nb = 0; nb < 8; nb++) {
        int col = nh * 64 + nb * 8 + 2 * c;
        float bb0 = is_drug ? __ldg(&b1[col])     : 0.0f;
        float bb1 = is_drug ? __ldg(&b1[col + 1]) : 0.0f;
        if (r0 < n)
            *(uint32_t*)((char*)out + (long)r0 * 256 + col * 2) =
                h2(acc[nb][0] + bb0, acc[nb][1] + bb1);
        if (r1 < n)
            *(uint32_t*)((char*)out + (long)r1 * 256 + col * 2) =
                h2(acc[nb][2] + bb0, acc[nb][3] + bb1);
    }
}

// ---------------------------------------------------------------------------
// Kernel 2: persistent per-edge MLP (unchanged from R11/R12 winner).
// ---------------------------------------------------------------------------
#define EPB   128
#define NTHR  256
#define HS_RS 272                       // bytes per hs row (256 + 16 pad)

__global__ void __launch_bounds__(NTHR, 3)
edge_mlp_kernel(const void* __restrict__ ell,
                const float* __restrict__ W2, const float* __restrict__ b2,
                const float* __restrict__ W3, const float* __restrict__ b3,
                const float* __restrict__ W4, const float* __restrict__ b4,
                float* __restrict__ out, int E, int n_tiles) {
    __shared__ char  hsraw[8 * 16 * HS_RS];   // 34816 B
    __shared__ uint4 wfr[8 * 2 * 32];         // W2 frags: [ks8][nbp2][lane]

    const int tid  = threadIdx.x;
    const int warp = tid >> 5;
    const int lane = tid & 31;
    const int is64 = g_idx64;

    for (int idx = tid; idx < 512; idx += NTHR) {
        int ln  = idx & 31;
        int nbp = (idx >> 5) & 1;
        int ks  = idx >> 6;
        int n0  = 16 * nbp + (ln >> 2);
        int n1  = n0 + 8;
        int kb  = 16 * ks + 2 * (ln & 3);
        uint4 b;
        b.x = h2(W2[kb * 32 + n0],       W2[(kb + 1) * 32 + n0]);
        b.y = h2(W2[(kb + 8) * 32 + n0], W2[(kb + 9) * 32 + n0]);
        b.z = h2(W2[kb * 32 + n1],       W2[(kb + 1) * 32 + n1]);
        b.w = h2(W2[(kb + 8) * 32 + n1], W2[(kb + 9) * 32 + n1]);
        wfr[idx] = b;
    }
    __syncthreads();

    const int g = lane >> 2;
    const int c = lane & 3;

    float b2r[4][2];
#pragma unroll
    for (int nb = 0; nb < 4; nb++) {
        b2r[nb][0] = __ldg(&b2[8 * nb + 2 * c + 0]);
        b2r[nb][1] = __ldg(&b2[8 * nb + 2 * c + 1]);
    }
    uint32_t w3f[2][2][2];
#pragma unroll
    for (int ks3 = 0; ks3 < 2; ks3++)
#pragma unroll
        for (int nb3 = 0; nb3 < 2; nb3++) {
            int n  = 8 * nb3 + g;
            int kb = 16 * ks3 + 2 * c;
            w3f[ks3][nb3][0] = h2(__ldg(&W3[kb * 16 + n]),
                                  __ldg(&W3[(kb + 1) * 16 + n]));
            w3f[ks3][nb3][1] = h2(__ldg(&W3[(kb + 8) * 16 + n]),
                                  __ldg(&W3[(kb + 9) * 16 + n]));
        }
    float b3r[2][2], w4r[2][2];
#pragma unroll
    for (int o = 0; o < 2; o++) {
        b3r[o][0] = __ldg(&b3[8 * o + 2 * c + 0]);
        b3r[o][1] = __ldg(&b3[8 * o + 2 * c + 1]);
        w4r[o][0] = __ldg(&W4[8 * o + 2 * c + 0]);
        w4r[o][1] = __ldg(&W4[8 * o + 2 * c + 1]);
    }
    const float b4v = __ldg(&b4[0]);
    const __half2 c01 = __float2half2_rn(0.01f);

    char* hw = hsraw + warp * 16 * HS_RS;
    const char* hdb = (const char*)g_hd;
    const char* heb = (const char*)g_he;

    const int half = lane >> 4;
    const int sub  = lane & 15;
    const uint32_t boff = (uint32_t)(sub << 4);

    for (int tile = blockIdx.x; tile < n_tiles; tile += gridDim.x) {
        const int ebase = tile * EPB + warp * 16;

        {
            int e  = ebase + (lane & 15);
            int ec = e < E ? e : (E - 1);
            long long pos = (lane < 16) ? (long long)ec : (long long)E + ec;
            int vi = (int)load_idx(ell, pos, is64);

#pragma unroll
            for (int t = 0; t < 8; t++) {
                int r = 2 * t + half;
                uint32_t i = (uint32_t)__shfl_sync(0xffffffffu, vi, r);
                uint32_t j = (uint32_t)__shfl_sync(0xffffffffu, vi, r + 16);
                const uint4 a = *(const uint4*)(hdb + (i << 8) + boff);
                const uint4 b = *(const uint4*)(heb + (j << 8) + boff);
                uint4 s;
                s.x = haddlrelu2(a.x, b.x, c01);
                s.y = haddlrelu2(a.y, b.y, c01);
                s.z = haddlrelu2(a.z, b.z, c01);
                s.w = haddlrelu2(a.w, b.w, c01);
                *(uint4*)(hw + r * HS_RS + boff) = s;
            }
        }
        __syncwarp();

        float acc[4][4];
#pragma unroll
        for (int nb = 0; nb < 4; nb++)
#pragma unroll
            for (int q = 0; q < 4; q++) acc[nb][q] = 0.0f;

        {
            const char* r0 = hw + g * HS_RS + 4 * c;
            const char* r1 = r0 + 8 * HS_RS;
#pragma unroll
            for (int ks = 0; ks < 8; ks++) {
                uint32_t a0 = *(const uint32_t*)(r0 + 32 * ks);
                uint32_t a1 = *(const uint32_t*)(r1 + 32 * ks);
                uint32_t a2 = *(const uint32_t*)(r0 + 32 * ks + 16);
                uint32_t a3 = *(const uint32_t*)(r1 + 32 * ks + 16);
#pragma unroll
                for (int nbp = 0; nbp < 2; nbp++) {
                    uint4 bb = wfr[(ks * 2 + nbp) * 32 + lane];
                    hmma16(acc[2 * nbp],     a0, a1, a2, a3, bb.x, bb.y);
                    hmma16(acc[2 * nbp + 1], a0, a1, a2, a3, bb.z, bb.w);
                }
            }
        }
        __syncwarp();

        float acc3[2][4];
#pragma unroll
        for (int o = 0; o < 2; o++)
#pragma unroll
            for (int q = 0; q < 4; q++) acc3[o][q] = 0.0f;

#pragma unroll
        for (int ks3 = 0; ks3 < 2; ks3++) {
            const int nbA = 2 * ks3;
            const int nbB = 2 * ks3 + 1;
            uint32_t a0 = h2(lrelu(acc[nbA][0] + b2r[nbA][0]),
                             lrelu(acc[nbA][1] + b2r[nbA][1]));
            uint32_t a1 = h2(lrelu(acc[nbA][2] + b2r[nbA][0]),
                             lrelu(acc[nbA][3] + b2r[nbA][1]));
            uint32_t a2 = h2(lrelu(acc[nbB][0] + b2r[nbB][0]),
                             lrelu(acc[nbB][1] + b2r[nbB][1]));
            uint32_t a3 = h2(lrelu(acc[nbB][2] + b2r[nbB][0]),
                             lrelu(acc[nbB][3] + b2r[nbB][1]));
#pragma unroll
            for (int nb3 = 0; nb3 < 2; nb3++)
                hmma16(acc3[nb3], a0, a1, a2, a3,
                       w3f[ks3][nb3][0], w3f[ks3][nb3][1]);
        }

        {
            float y0 = 0.0f, y1 = 0.0f;
#pragma unroll
            for (int o = 0; o < 2; o++) {
                y0 = fmaf(lrelu(acc3[o][0] + b3r[o][0]), w4r[o][0], y0);
                y0 = fmaf(lrelu(acc3[o][1] + b3r[o][1]), w4r[o][1], y0);
                y1 = fmaf(lrelu(acc3[o][2] + b3r[o][0]), w4r[o][0], y1);
                y1 = fmaf(lrelu(acc3[o][3] + b3r[o][1]), w4r[o][1], y1);
            }
            y0 += __shfl_xor_sync(0xffffffffu, y0, 1);
            y0 += __shfl_xor_sync(0xffffffffu, y0, 2);
            y1 += __shfl_xor_sync(0xffffffffu, y1, 1);
            y1 += __shfl_xor_sync(0xffffffffu, y1, 2);

            if (c == 0) {
                int e0 = ebase + g;
                if (e0 < E)     out[e0]     = y0 + b4v;
                if (e0 + 8 < E) out[e0 + 8] = y1 + b4v;
            }
        }
    }
}

// ---------------------------------------------------------------------------
extern "C" void kernel_launch(void* const* d_in, const int* in_sizes, int n_in,
                              void* d_out, int out_size) {
    const float* xd  = (const float*)d_in[0];
    const float* xs  = (const float*)d_in[1];
    const void*  ell = d_in[2];
    const float* W1  = (const float*)d_in[3];
    const float* b1  = (const float*)d_in[4];
    const float* W2  = (const float*)d_in[5];
    const float* b2  = (const float*)d_in[6];
    const float* W3  = (const float*)d_in[7];
    const float* b3  = (const float*)d_in[8];
    const float* W4  = (const float*)d_in[9];
    const float* b4  = (const float*)d_in[10];
    float* out = (float*)d_out;

    int n_drug = in_sizes[0] / 100;
    int n_dis  = in_sizes[1] / 100;
    int E      = in_sizes[2] / 2;

    w1_frag_prep<<<2, 256>>>(W1, (const long long*)ell);

    int nb_drug = (n_drug + NNB - 1) / NNB;
    int nb_dis  = (n_dis  + NNB - 1) / NNB;
    node_precompute<<<nb_drug + nb_dis, 256>>>(xd, xs, b1,
                                               n_drug, n_dis, nb_drug);

    int n_tiles = (E + EPB - 1) / EPB;
    int grid = 3 * 148;
    if (grid > n_tiles) grid = n_tiles;
    edge_mlp_kernel<<<grid, NTHR>>>(ell, W2, b2, W3, b3, W4, b4,
                                    out, E, n_tiles);
}

// round 14
// speedup vs baseline: 4.2106x; 1.0514x over previous
#include <cuda_runtime.h>
#include <cuda_bf16.h>
#include <cuda_fp16.h>
#include <cstdint>

// ---------------------------------------------------------------------------
// Classifier: out[e] = MLP(concat(x_drug[i_e], x_disease[j_e]))
// Layer-1 factored per-node, computed on tensor cores with hi/lo fp16 split
// (x = xh+xl, W1 = Wh+Wl; acc = xh@Wh + xl@Wh + xh@Wl in fp32 -> err ~1e-7):
//   h_drug    = x_drug    @ W1[0:100]   + b1     (n_drug x 128, fp16 tables)
//   h_disease = x_disease @ W1[100:200]          (n_dis  x 128)
// W1 fragments built ONCE by a 14-block prep kernel (coalesced smem-staged);
// node blocks read them coalesced from L2. Per edge: h = lrelu(hd[i]+he[j])
// in half2 -> fp16 smem; layers 2/3 on mma.m16n8k16.f16 (fp32 accum) with
// composing fragment layouts; layer-4 dot + shfl reduce. Warp-autonomous.
// ---------------------------------------------------------------------------

typedef unsigned long long ull;

#define MAX_NODES 16384
__device__ __half g_hd[MAX_NODES * 128];
__device__ __half g_he[MAX_NODES * 128];
__device__ int    g_idx64;   // 1 if edge index buffer is int64, 0 if int32

#define NFRAG (7 * 16 * 32)              // 3584 uint2 per set
__device__ uint2 g_whf[2][NFRAG];        // [0]=drug slice, [1]=disease slice
__device__ uint2 g_wlf[2][NFRAG];

__device__ __forceinline__ float lrelu(float v) {
    return v >= 0.0f ? v : 0.01f * v;
}
__device__ __forceinline__ uint32_t h2(float a, float b) {
    __half2 h = __floats2half2_rn(a, b);   // x(lo)=a, y(hi)=b
    return *(uint32_t*)&h;
}
// packed fp16 add + leaky-relu: lrelu(x) == max(x, 0.01*x) elementwise
__device__ __forceinline__ uint32_t haddlrelu2(uint32_t a, uint32_t b,
                                               __half2 c01) {
    __half2 s = __hadd2(*(__half2*)&a, *(__half2*)&b);
    __half2 r = __hmax2(s, __hmul2(s, c01));
    return *(uint32_t*)&r;
}
__device__ __forceinline__ long long load_idx(const void* ell, long long pos,
                                              int is64) {
    if (is64) return ((const long long*)ell)[pos];
    return (long long)((const int*)ell)[pos];
}

// m16n8k16 f16 MMA (row.col), fp32 accumulate in place
__device__ __forceinline__ void hmma16(float d[4], uint32_t a0, uint32_t a1,
                                       uint32_t a2, uint32_t a3,
                                       uint32_t b0, uint32_t b1) {
    asm volatile(
        "mma.sync.aligned.m16n8k16.row.col.f32.f16.f16.f32 "
        "{%0,%1,%2,%3}, {%4,%5,%6,%7}, {%8,%9}, {%0,%1,%2,%3};"
        : "+f"(d[0]), "+f"(d[1]), "+f"(d[2]), "+f"(d[3])
        : "r"(a0), "r"(a1), "r"(a2), "r"(a3), "r"(b0), "r"(b1));
}

// ---------------------------------------------------------------------------
// Kernel 0: one-time W1 hi/lo fragment build.
// grid = 14 blocks: block b -> (sel = b/7, ks = b%7). Each block coalesced-
// loads its 16 k-rows (8 KB) into smem, then builds its 512 frag uint2 from
// smem. Block 0 also detects the edge-index dtype (JAX w/o x64 -> int32).
// ---------------------------------------------------------------------------
__global__ void w1_frag_prep(const float* __restrict__ W1,
                             const long long* __restrict__ ell) {
    __shared__ float wsl[16 * 128];

    const int tid = threadIdx.x;
    const int sel = blockIdx.x / 7;
    const int ks  = blockIdx.x % 7;

    if (blockIdx.x == 0 && tid == 0) {
        int ok64 = 1;
#pragma unroll
        for (int t = 0; t < 8; t++) {
            long long v = ell[t];
            if (v < 0 || v >= 1000000) ok64 = 0;
        }
        g_idx64 = ok64;
    }

    const float* w = W1 + sel * 100 * 128 + 16 * ks * 128;
    const int krows = (100 - 16 * ks) < 16 ? (100 - 16 * ks) : 16;

    // coalesced float4 stage of 16 x 128 rows (zero-pad beyond k=100)
    for (int i = tid; i < 16 * 32; i += 256) {
        float4 v = make_float4(0.f, 0.f, 0.f, 0.f);
        if ((i >> 5) < krows) v = ((const float4*)w)[i];
        ((float4*)wsl)[i] = v;
    }
    __syncthreads();

    // build 512 fragments for this (sel, ks)
    for (int i = tid; i < 512; i += 256) {
        int ln = i & 31;
        int nb = i >> 5;                 // 0..15
        int nn = 8 * nb + (ln >> 2);
        int kb = 2 * (ln & 3);           // local k within the 16-row slab
        float f[4], fh[4];
#pragma unroll
        for (int q = 0; q < 4; q++) {
            int k = kb + (q >> 1) * 8 + (q & 1);
            f[q]  = wsl[k * 128 + nn];
            fh[q] = __half2float(__float2half_rn(f[q]));
        }
        int gi = ks * 512 + i;
        g_whf[sel][gi] = make_uint2(h2(f[0], f[1]), h2(f[2], f[3]));
        g_wlf[sel][gi] = make_uint2(h2(f[0] - fh[0], f[1] - fh[1]),
                                    h2(f[2] - fh[2], f[3] - fh[3]));
    }
}

// ---------------------------------------------------------------------------
// Kernel 1: layer-1 precompute on tensor cores. 64 nodes/block, 256 threads.
// K = 100 padded to 112 (7 k16-steps). Split-precision: 3 mma passes.
// smem: xh/xl only (30 KB); W1 frags read coalesced from global (L2-hot).
// ---------------------------------------------------------------------------
#define NNB   64
#define XS_RS 240                              // 112 halves = 224B + 16 pad

__global__ void __launch_bounds__(256, 4)
node_precompute(const float* __restrict__ xd,
                const float* __restrict__ xs,
                const float* __restrict__ b1,
                int n_drug, int n_dis, int nb_drug) {
    __shared__ char xh[NNB * XS_RS];
    __shared__ char xl[NNB * XS_RS];

    const int tid = threadIdx.x;
    const int bid = blockIdx.x;

    const bool is_drug = bid < nb_drug;
    const int  sel     = is_drug ? 0 : 1;
    const int  n       = is_drug ? n_drug : n_dis;
    const int  nbase   = (is_drug ? bid : bid - nb_drug) * NNB;
    const float* x   = is_drug ? xd : xs;
    __half*      out = is_drug ? g_hd : g_he;

    // ---- stage x hi/lo: 64 rows x 56 u32 (112 halves) ----
    for (int i = tid; i < NNB * 56; i += 256) {
        int row = i / 56;
        int p   = i - row * 56;
        int gn  = nbase + row;
        int k0  = 2 * p;
        float v0 = 0.0f, v1 = 0.0f;
        if (gn < n) {
            if (k0 < 100)     v0 = x[(long)gn * 100 + k0];
            if (k0 + 1 < 100) v1 = x[(long)gn * 100 + k0 + 1];
        }
        float h0 = __half2float(__float2half_rn(v0));
        float h1 = __half2float(__float2half_rn(v1));
        *(uint32_t*)(xh + row * XS_RS + 4 * p) = h2(v0, v1);
        *(uint32_t*)(xl + row * XS_RS + 4 * p) = h2(v0 - h0, v1 - h1);
    }
    __syncthreads();

    // ---- mma: warp -> (m-tile mt = warp&3, n-half nh = warp>>2) ----
    const int warp = tid >> 5;
    const int lane = tid & 31;
    const int g = lane >> 2;
    const int c = lane & 3;
    const int mt = warp & 3;
    const int nh = warp >> 2;

    const char* axh = xh + (mt * 16 + g) * XS_RS + 4 * c;
    const char* axl = xl + (mt * 16 + g) * XS_RS + 4 * c;
    const uint2* whf = g_whf[sel];
    const uint2* wlf = g_wlf[sel];

    float acc[8][4];
#pragma unroll
    for (int nb = 0; nb < 8; nb++)
#pragma unroll
        for (int q = 0; q < 4; q++) acc[nb][q] = 0.0f;

#pragma unroll
    for (int ks = 0; ks < 7; ks++) {
        uint32_t ah0 = *(const uint32_t*)(axh + 32 * ks);
        uint32_t ah1 = *(const uint32_t*)(axh + 32 * ks + 8 * XS_RS);
        uint32_t ah2 = *(const uint32_t*)(axh + 32 * ks + 16);
        uint32_t ah3 = *(const uint32_t*)(axh + 32 * ks + 8 * XS_RS + 16);
        uint32_t al0 = *(const uint32_t*)(axl + 32 * ks);
        uint32_t al1 = *(const uint32_t*)(axl + 32 * ks + 8 * XS_RS);
        uint32_t al2 = *(const uint32_t*)(axl + 32 * ks + 16);
        uint32_t al3 = *(const uint32_t*)(axl + 32 * ks + 8 * XS_RS + 16);
#pragma unroll
        for (int nb = 0; nb < 8; nb++) {
            int fi = (ks * 16 + nh * 8 + nb) * 32 + lane;
            uint2 bh = __ldg(&whf[fi]);
            uint2 bl = __ldg(&wlf[fi]);
            hmma16(acc[nb], ah0, ah1, ah2, ah3, bh.x, bh.y);
            hmma16(acc[nb], al0, al1, al2, al3, bh.x, bh.y);
            hmma16(acc[nb], ah0, ah1, ah2, ah3, bl.x, bl.y);
        }
    }

    // ---- epilogue: +b1 (drug only), pack fp16 pairs, store ----
    int r0 = nbase + mt * 16 + g;
    int r1 = r0 + 8;
#pragma unroll
    for (int nb = 0; nb < 8; nb++) {
        int col = nh * 64 + nb * 8 + 2 * c;
        float bb0 = is_drug ? __ldg(&b1[col])     : 0.0f;
        float bb1 = is_drug ? __ldg(&b1[col + 1]) : 0.0f;
        if (r0 < n)
            *(uint32_t*)((char*)out + (long)r0 * 256 + col * 2) =
                h2(acc[nb][0] + bb0, acc[nb][1] + bb1);
        if (r1 < n)
            *(uint32_t*)((char*)out + (long)r1 * 256 + col * 2) =
                h2(acc[nb][2] + bb0, acc[nb][3] + bb1);
    }
}

// ---------------------------------------------------------------------------
// Kernel 2: persistent per-edge MLP (unchanged from R11-R13 winner).
// ---------------------------------------------------------------------------
#define EPB   128
#define NTHR  256
#define HS_RS 272                       // bytes per hs row (256 + 16 pad)

__global__ void __launch_bounds__(NTHR, 3)
edge_mlp_kernel(const void* __restrict__ ell,
                const float* __restrict__ W2, const float* __restrict__ b2,
                const float* __restrict__ W3, const float* __restrict__ b3,
                const float* __restrict__ W4, const float* __restrict__ b4,
                float* __restrict__ out, int E, int n_tiles) {
    __shared__ char  hsraw[8 * 16 * HS_RS];   // 34816 B
    __shared__ uint4 wfr[8 * 2 * 32];         // W2 frags: [ks8][nbp2][lane]

    const int tid  = threadIdx.x;
    const int warp = tid >> 5;
    const int lane = tid & 31;
    const int is64 = g_idx64;

    for (int idx = tid; idx < 512; idx += NTHR) {
        int ln  = idx & 31;
        int nbp = (idx >> 5) & 1;
        int ks  = idx >> 6;
        int n0  = 16 * nbp + (ln >> 2);
        int n1  = n0 + 8;
        int kb  = 16 * ks + 2 * (ln & 3);
        uint4 b;
        b.x = h2(W2[kb * 32 + n0],       W2[(kb + 1) * 32 + n0]);
        b.y = h2(W2[(kb + 8) * 32 + n0], W2[(kb + 9) * 32 + n0]);
        b.z = h2(W2[kb * 32 + n1],       W2[(kb + 1) * 32 + n1]);
        b.w = h2(W2[(kb + 8) * 32 + n1], W2[(kb + 9) * 32 + n1]);
        wfr[idx] = b;
    }
    __syncthreads();

    const int g = lane >> 2;
    const int c = lane & 3;

    float b2r[4][2];
#pragma unroll
    for (int nb = 0; nb < 4; nb++) {
        b2r[nb][0] = __ldg(&b2[8 * nb + 2 * c + 0]);
        b2r[nb][1] = __ldg(&b2[8 * nb + 2 * c + 1]);
    }
    uint32_t w3f[2][2][2];
#pragma unroll
    for (int ks3 = 0; ks3 < 2; ks3++)
#pragma unroll
        for (int nb3 = 0; nb3 < 2; nb3++) {
            int n  = 8 * nb3 + g;
            int kb = 16 * ks3 + 2 * c;
            w3f[ks3][nb3][0] = h2(__ldg(&W3[kb * 16 + n]),
                                  __ldg(&W3[(kb + 1) * 16 + n]));
            w3f[ks3][nb3][1] = h2(__ldg(&W3[(kb + 8) * 16 + n]),
                                  __ldg(&W3[(kb + 9) * 16 + n]));
        }
    float b3r[2][2], w4r[2][2];
#pragma unroll
    for (int o = 0; o < 2; o++) {
        b3r[o][0] = __ldg(&b3[8 * o + 2 * c + 0]);
        b3r[o][1] = __ldg(&b3[8 * o + 2 * c + 1]);
        w4r[o][0] = __ldg(&W4[8 * o + 2 * c + 0]);
        w4r[o][1] = __ldg(&W4[8 * o + 2 * c + 1]);
    }
    const float b4v = __ldg(&b4[0]);
    const __half2 c01 = __float2half2_rn(0.01f);

    char* hw = hsraw + warp * 16 * HS_RS;
    const char* hdb = (const char*)g_hd;
    const char* heb = (const char*)g_he;

    const int half = lane >> 4;
    const int sub  = lane & 15;
    const uint32_t boff = (uint32_t)(sub << 4);

    for (int tile = blockIdx.x; tile < n_tiles; tile += gridDim.x) {
        const int ebase = tile * EPB + warp * 16;

        {
            int e  = ebase + (lane & 15);
            int ec = e < E ? e : (E - 1);
            long long pos = (lane < 16) ? (long long)ec : (long long)E + ec;
            int vi = (int)load_idx(ell, pos, is64);

#pragma unroll
            for (int t = 0; t < 8; t++) {
                int r = 2 * t + half;
                uint32_t i = (uint32_t)__shfl_sync(0xffffffffu, vi, r);
                uint32_t j = (uint32_t)__shfl_sync(0xffffffffu, vi, r + 16);
                const uint4 a = *(const uint4*)(hdb + (i << 8) + boff);
                const uint4 b = *(const uint4*)(heb + (j << 8) + boff);
                uint4 s;
                s.x = haddlrelu2(a.x, b.x, c01);
                s.y = haddlrelu2(a.y, b.y, c01);
                s.z = haddlrelu2(a.z, b.z, c01);
                s.w = haddlrelu2(a.w, b.w, c01);
                *(uint4*)(hw + r * HS_RS + boff) = s;
            }
        }
        __syncwarp();

        float acc[4][4];
#pragma unroll
        for (int nb = 0; nb < 4; nb++)
#pragma unroll
            for (int q = 0; q < 4; q++) acc[nb][q] = 0.0f;

        {
            const char* r0 = hw + g * HS_RS + 4 * c;
            const char* r1 = r0 + 8 * HS_RS;
#pragma unroll
            for (int ks = 0; ks < 8; ks++) {
                uint32_t a0 = *(const uint32_t*)(r0 + 32 * ks);
                uint32_t a1 = *(const uint32_t*)(r1 + 32 * ks);
                uint32_t a2 = *(const uint32_t*)(r0 + 32 * ks + 16);
                uint32_t a3 = *(const uint32_t*)(r1 + 32 * ks + 16);
#pragma unroll
                for (int nbp = 0; nbp < 2; nbp++) {
                    uint4 bb = wfr[(ks * 2 + nbp) * 32 + lane];
                    hmma16(acc[2 * nbp],     a0, a1, a2, a3, bb.x, bb.y);
                    hmma16(acc[2 * nbp + 1], a0, a1, a2, a3, bb.z, bb.w);
                }
            }
        }
        __syncwarp();

        float acc3[2][4];
#pragma unroll
        for (int o = 0; o < 2; o++)
#pragma unroll
            for (int q = 0; q < 4; q++) acc3[o][q] = 0.0f;

#pragma unroll
        for (int ks3 = 0; ks3 < 2; ks3++) {
            const int nbA = 2 * ks3;
            const int nbB = 2 * ks3 + 1;
            uint32_t a0 = h2(lrelu(acc[nbA][0] + b2r[nbA][0]),
                             lrelu(acc[nbA][1] + b2r[nbA][1]));
            uint32_t a1 = h2(lrelu(acc[nbA][2] + b2r[nbA][0]),
                             lrelu(acc[nbA][3] + b2r[nbA][1]));
            uint32_t a2 = h2(lrelu(acc[nbB][0] + b2r[nbB][0]),
                             lrelu(acc[nbB][1] + b2r[nbB][1]));
            uint32_t a3 = h2(lrelu(acc[nbB][2] + b2r[nbB][0]),
                             lrelu(acc[nbB][3] + b2r[nbB][1]));
#pragma unroll
            for (int nb3 = 0; nb3 < 2; nb3++)
                hmma16(acc3[nb3], a0, a1, a2, a3,
                       w3f[ks3][nb3][0], w3f[ks3][nb3][1]);
        }

        {
            float y0 = 0.0f, y1 = 0.0f;
#pragma unroll
            for (int o = 0; o < 2; o++) {
                y0 = fmaf(lrelu(acc3[o][0] + b3r[o][0]), w4r[o][0], y0);
                y0 = fmaf(lrelu(acc3[o][1] + b3r[o][1]), w4r[o][1], y0);
                y1 = fmaf(lrelu(acc3[o][2] + b3r[o][0]), w4r[o][0], y1);
                y1 = fmaf(lrelu(acc3[o][3] + b3r[o][1]), w4r[o][1], y1);
            }
            y0 += __shfl_xor_sync(0xffffffffu, y0, 1);
            y0 += __shfl_xor_sync(0xffffffffu, y0, 2);
            y1 += __shfl_xor_sync(0xffffffffu, y1, 1);
            y1 += __shfl_xor_sync(0xffffffffu, y1, 2);

            if (c == 0) {
                int e0 = ebase + g;
                if (e0 < E)     out[e0]     = y0 + b4v;
                if (e0 + 8 < E) out[e0 + 8] = y1 + b4v;
            }
        }
    }
}

// ---------------------------------------------------------------------------
extern "C" void kernel_launch(void* const* d_in, const int* in_sizes, int n_in,
                              void* d_out, int out_size) {
    const float* xd  = (const float*)d_in[0];
    const float* xs  = (const float*)d_in[1];
    const void*  ell = d_in[2];
    const float* W1  = (const float*)d_in[3];
    const float* b1  = (const float*)d_in[4];
    const float* W2  = (const float*)d_in[5];
    const float* b2  = (const float*)d_in[6];
    const float* W3  = (const float*)d_in[7];
    const float* b3  = (const float*)d_in[8];
    const float* W4  = (const float*)d_in[9];
    const float* b4  = (const float*)d_in[10];
    float* out = (float*)d_out;

    int n_drug = in_sizes[0] / 100;
    int n_dis  = in_sizes[1] / 100;
    int E      = in_sizes[2] / 2;

    w1_frag_prep<<<14, 256>>>(W1, (const long long*)ell);

    int nb_drug = (n_drug + NNB - 1) / NNB;
    int nb_dis  = (n_dis  + NNB - 1) / NNB;
    node_precompute<<<nb_drug + nb_dis, 256>>>(xd, xs, b1,
                                               n_drug, n_dis, nb_drug);

    int n_tiles = (E + EPB - 1) / EPB;
    int grid = 3 * 148;
    if (grid > n_tiles) grid = n_tiles;
    edge_mlp_kernel<<<grid, NTHR>>>(ell, W2, b2, W3, b3, W4, b4,
                                    out, E, n_tiles);
}